// round 8
// baseline (speedup 1.0000x reference)
#include <cuda_runtime.h>
#include <cuda_bf16.h>
#include <math.h>
#include <float.h>
#include <stdint.h>

#define NN 50000
#define NE 800000
#define NHEAD 4

// ---------------- scratch (device globals; no allocation allowed) ----------------
__device__ float g_z[(size_t)NN * 256];    // GEMM0/1 output (projected feats, fp32)
__device__ float g_h[(size_t)NN * 256];    // hidden activations (fp32, for scores/agg)
__device__ __nv_bfloat16 g_ahi[(size_t)NN * 1024];  // GEMM A operand, bf16 high part
__device__ __nv_bfloat16 g_alo[(size_t)NN * 1024];  // GEMM A operand, bf16 low part
__device__ __nv_bfloat16 g_bthi[256 * 1024];        // GEMM B operand [N,K] K-major, hi
__device__ __nv_bfloat16 g_btlo[256 * 1024];        // GEMM B operand [N,K] K-major, lo
__device__ float g_el[NN * NHEAD];
__device__ float g_er[NN * NHEAD];
__device__ int   g_ss[NE];                     // src node per sorted edge
__device__ int   g_deg[NN];
__device__ int   g_cur[NN];
__device__ int   g_off[NN + 1];
__device__ float g_wl2[NHEAD * 256];
__device__ float g_wr2[NHEAD * 256];
__device__ float g_bias2[256];

// ================= warp-MMA helpers (sm_80+ PTX, works under compute_103) =================
__device__ __forceinline__ uint32_t smem_u32(const void* p) {
    uint32_t a;
    asm("{ .reg .u64 t; cvta.to.shared.u64 t, %1; cvt.u32.u64 %0, t; }" : "=r"(a) : "l"(p));
    return a;
}
#define LDM4(r0, r1, r2, r3, addr) \
    asm volatile("ldmatrix.sync.aligned.m8n8.x4.shared.b16 {%0,%1,%2,%3}, [%4];" \
                 : "=r"(r0), "=r"(r1), "=r"(r2), "=r"(r3) : "r"(addr))
#define MMA16816(d, a, b) \
    asm volatile("mma.sync.aligned.m16n8k16.row.col.f32.bf16.bf16.f32 " \
                 "{%0,%1,%2,%3}, {%4,%5,%6,%7}, {%8,%9}, {%0,%1,%2,%3};" \
                 : "+f"((d)[0]), "+f"((d)[1]), "+f"((d)[2]), "+f"((d)[3]) \
                 : "r"((a)[0]), "r"((a)[1]), "r"((a)[2]), "r"((a)[3]), \
                   "r"((b)[0]), "r"((b)[1]))

// ================= split-bf16 tensor-core GEMM, register-prefetch double buffer =================
// (unchanged from R7 — proven fastest)
#define GBM 128
#define GBN 128
#define GBK 32
#define GPAD 40

__global__ void __launch_bounds__(256)
k_gemm_mma(const __nv_bfloat16* __restrict__ Ahi, const __nv_bfloat16* __restrict__ Alo,
           const __nv_bfloat16* __restrict__ Bhi, const __nv_bfloat16* __restrict__ Blo,
           float* __restrict__ C, int M, int N, int K,
           float scale, const float* __restrict__ bias) {
    __shared__ __nv_bfloat16 sAhi[GBM * GPAD];
    __shared__ __nv_bfloat16 sAlo[GBM * GPAD];
    __shared__ __nv_bfloat16 sBhi[GBN * GPAD];
    __shared__ __nv_bfloat16 sBlo[GBN * GPAD];

    int tid = threadIdx.x;
    int lane = tid & 31;
    int wid = tid >> 5;
    int wm = wid >> 2;
    int wn = wid & 3;
    int bm = blockIdx.y * GBM;
    int bn = blockIdx.x * GBN;

    uint32_t bAhi = smem_u32(sAhi), bAlo = smem_u32(sAlo);
    uint32_t bBhi = smem_u32(sBhi), bBlo = smem_u32(sBlo);

    const __nv_bfloat16* gptr[8];
    __nv_bfloat16* sptr[8];
    bool valid[8];
#pragma unroll
    for (int t = 0; t < 8; t++) {
        int idx = tid + t * 256;
        int tile = idx >> 9;
        int u = idx & 511;
        int row = u >> 2;
        int ch = u & 3;
        __nv_bfloat16* sbase = (tile == 0) ? sAhi : (tile == 1) ? sAlo : (tile == 2) ? sBhi : sBlo;
        sptr[t] = sbase + row * GPAD + ch * 8;
        if (tile < 2) {
            int gm = bm + row;
            valid[t] = (gm < M);
            const __nv_bfloat16* gb = (tile == 0) ? Ahi : Alo;
            gptr[t] = gb + (size_t)(valid[t] ? gm : 0) * K + ch * 8;
        } else {
            int gn = bn + row;
            valid[t] = true;
            const __nv_bfloat16* gb = (tile == 2) ? Bhi : Blo;
            gptr[t] = gb + (size_t)gn * K + ch * 8;
        }
    }

    float acc[4][4][4];
#pragma unroll
    for (int i = 0; i < 4; i++)
#pragma unroll
        for (int j = 0; j < 4; j++)
#pragma unroll
            for (int r = 0; r < 4; r++) acc[i][j][r] = 0.f;

    int lrow = lane & 15;
    int lcol = (lane >> 4) * 8;

    int nst = K / GBK;
    uint4 pre[8];
#pragma unroll
    for (int t = 0; t < 8; t++)
        pre[t] = valid[t] ? *reinterpret_cast<const uint4*>(gptr[t]) : make_uint4(0, 0, 0, 0);

    for (int s = 0; s < nst; s++) {
#pragma unroll
        for (int t = 0; t < 8; t++) *reinterpret_cast<uint4*>(sptr[t]) = pre[t];
        __syncthreads();

        if (s + 1 < nst) {
            int k0 = (s + 1) * GBK;
#pragma unroll
            for (int t = 0; t < 8; t++)
                pre[t] = valid[t] ? *reinterpret_cast<const uint4*>(gptr[t] + k0)
                                  : make_uint4(0, 0, 0, 0);
        }

#pragma unroll
        for (int kk = 0; kk < 2; kk++) {
            int kb = kk * 16;
            uint32_t ahi[4][4], alo[4][4];
#pragma unroll
            for (int i = 0; i < 4; i++) {
                uint32_t off = (uint32_t)((wm * 64 + i * 16 + lrow) * GPAD + kb + lcol) * 2;
                LDM4(ahi[i][0], ahi[i][1], ahi[i][2], ahi[i][3], bAhi + off);
                LDM4(alo[i][0], alo[i][1], alo[i][2], alo[i][3], bAlo + off);
            }
            uint32_t bhi[4][2], blo[4][2];
#pragma unroll
            for (int j = 0; j < 2; j++) {
                uint32_t off = (uint32_t)((wn * 32 + j * 16 + lrow) * GPAD + kb + lcol) * 2;
                uint32_t r0, r1, r2, r3;
                LDM4(r0, r1, r2, r3, bBhi + off);
                bhi[2 * j][0] = r0; bhi[2 * j][1] = r2;
                bhi[2 * j + 1][0] = r1; bhi[2 * j + 1][1] = r3;
                LDM4(r0, r1, r2, r3, bBlo + off);
                blo[2 * j][0] = r0; blo[2 * j][1] = r2;
                blo[2 * j + 1][0] = r1; blo[2 * j + 1][1] = r3;
            }
#pragma unroll
            for (int i = 0; i < 4; i++)
#pragma unroll
                for (int n = 0; n < 4; n++) {
                    MMA16816(acc[i][n], ahi[i], bhi[n]);
                    MMA16816(acc[i][n], ahi[i], blo[n]);
                    MMA16816(acc[i][n], alo[i], bhi[n]);
                }
        }
        __syncthreads();
    }

    int g = lane >> 2, tg = lane & 3;
#pragma unroll
    for (int mi = 0; mi < 4; mi++) {
        int r0 = bm + wm * 64 + mi * 16 + g;
        int r1 = r0 + 8;
#pragma unroll
        for (int ni = 0; ni < 4; ni++) {
            int c = bn + wn * 32 + ni * 8 + tg * 2;
            float b0 = 0.f, b1 = 0.f;
            if (bias) { b0 = bias[c]; b1 = bias[c + 1]; }
            if (r0 < M) {
                float2 v = make_float2(scale * acc[mi][ni][0] + b0,
                                       scale * acc[mi][ni][1] + b1);
                *reinterpret_cast<float2*>(&C[(size_t)r0 * N + c]) = v;
            }
            if (r1 < M) {
                float2 v = make_float2(scale * acc[mi][ni][2] + b0,
                                       scale * acc[mi][ni][3] + b1);
                *reinterpret_cast<float2*>(&C[(size_t)r1 * N + c]) = v;
            }
        }
    }
}

// ================= bf16 split conversions =================
__global__ void k_splitA(const float* __restrict__ in, __nv_bfloat16* __restrict__ hi,
                         __nv_bfloat16* __restrict__ lo, int count) {
    int i = blockIdx.x * blockDim.x + threadIdx.x;
    if (i >= count) return;
    float f = in[i];
    __nv_bfloat16 h = __float2bfloat16(f);
    hi[i] = h;
    lo[i] = __float2bfloat16(f - __bfloat162float(h));
}

__global__ void k_splitWt(const float* __restrict__ W, int K, int N) {
    int t = blockIdx.x * blockDim.x + threadIdx.x;
    if (t >= K * N) return;
    int n = t / K, k = t % K;
    float f = W[(size_t)k * N + n];
    __nv_bfloat16 h = __float2bfloat16(f);
    g_bthi[t] = h;
    g_btlo[t] = __float2bfloat16(f - __bfloat162float(h));
}

__global__ void k_splitW2(const float* __restrict__ W2) {
    int t = blockIdx.x * blockDim.x + threadIdx.x;
    if (t >= 256 * 1024) return;
    int c = t >> 10;
    int r = t & 1023;
    int h = r >> 8, kk = r & 255;
    float f = W2[(size_t)kk * 1024 + h * 256 + c];
    __nv_bfloat16 hh = __float2bfloat16(f);
    g_bthi[t] = hh;
    g_btlo[t] = __float2bfloat16(f - __bfloat162float(hh));
}

// ---------------- CSR build (by destination) ----------------
__global__ void k_zero_deg() {
    int i = blockIdx.x * blockDim.x + threadIdx.x;
    if (i < NN) g_deg[i] = 0;
}
__global__ void k_count(const int* __restrict__ dst) {
    int i = blockIdx.x * blockDim.x + threadIdx.x;
    if (i < NE) atomicAdd(&g_deg[dst[i]], 1);
}
// warp-shuffle scan: 2 barriers per 1024-chunk instead of 20
__global__ void k_scan() {
    __shared__ int warpsum[32];
    __shared__ int carry;
    int tid = threadIdx.x, lane = tid & 31, wrp = tid >> 5;
    if (tid == 0) carry = 0;
    __syncthreads();
    for (int base = 0; base < NN; base += 1024) {
        int i = base + tid;
        int v = (i < NN) ? g_deg[i] : 0;
        int x = v;
#pragma unroll
        for (int o = 1; o < 32; o <<= 1) {
            int t = __shfl_up_sync(0xffffffffu, x, o);
            if (lane >= o) x += t;
        }
        if (lane == 31) warpsum[wrp] = x;
        __syncthreads();
        if (wrp == 0) {
            int w = warpsum[lane];
#pragma unroll
            for (int o = 1; o < 32; o <<= 1) {
                int t = __shfl_up_sync(0xffffffffu, w, o);
                if (lane >= o) w += t;
            }
            warpsum[lane] = w;
        }
        __syncthreads();
        int excl = carry + (wrp ? warpsum[wrp - 1] : 0) + x - v;
        if (i < NN) {
            g_off[i] = excl;
            g_cur[i] = excl;
        }
        __syncthreads();   // all reads of carry/warpsum done
        if (tid == 0) carry += warpsum[31];
        __syncthreads();
    }
    if (tid == 0) g_off[NN] = carry;
}
__global__ void k_fill(const int* __restrict__ src, const int* __restrict__ dst) {
    int i = blockIdx.x * blockDim.x + threadIdx.x;
    if (i < NE) {
        int d = dst[i];
        int p = atomicAdd(&g_cur[d], 1);
        g_ss[p] = src[i];
    }
}

// ---------------- layer-2 precompute (wl2/wr2 + bias2 folded in) ----------------
__global__ void k_prep_scores(const float* __restrict__ W2, const float* __restrict__ al2,
                              const float* __restrict__ ar2, const float* __restrict__ b2) {
    int t = blockIdx.x * blockDim.x + threadIdx.x;
    if (t < 2048) {
        int which = t >> 10;
        int hk = t & 1023;
        int h = hk >> 8, k = hk & 255;
        const float* a = (which == 0 ? al2 : ar2) + h * 256;
        const float* wrow = W2 + (size_t)k * 1024 + h * 256;
        float s = 0.f;
#pragma unroll 8
        for (int c = 0; c < 256; c++) s += wrow[c] * a[c];
        if (which == 0) g_wl2[hk] = s;
        else            g_wr2[hk] = s;
    } else if (t < 2304) {
        int c = t - 2048;
        g_bias2[c] = 0.25f * (b2[c] + b2[256 + c] + b2[512 + c] + b2[768 + c]);
    }
}

// ---------------- per-node attention scores (layers 0/1, F=64) ----------------
__global__ void k_scores(const float* __restrict__ z, const float* __restrict__ al,
                         const float* __restrict__ ar) {
    int gw = (blockIdx.x * blockDim.x + threadIdx.x) >> 5;
    int lane = threadIdx.x & 31;
    if (gw >= NN) return;
    const float* row = z + (size_t)gw * 256;
    float accl[NHEAD], accr[NHEAD];
#pragma unroll
    for (int h = 0; h < NHEAD; h++) { accl[h] = 0.f; accr[h] = 0.f; }
#pragma unroll
    for (int i = 0; i < 8; i++) {
        int j = lane + 32 * i;
        float v = row[j];
        int h = i >> 1;
        accl[h] += v * al[j];
        accr[h] += v * ar[j];
    }
#pragma unroll
    for (int h = 0; h < NHEAD; h++) {
        float l = accl[h], r = accr[h];
#pragma unroll
        for (int o = 16; o > 0; o >>= 1) {
            l += __shfl_xor_sync(0xffffffffu, l, o);
            r += __shfl_xor_sync(0xffffffffu, r, o);
        }
        if (lane == 0) {
            g_el[gw * NHEAD + h] = l;
            g_er[gw * NHEAD + h] = r;
        }
    }
}

// ---------------- layer-2 scores directly from h1 ----------------
__global__ void k_scores2(const float* __restrict__ h1) {
    int gw = (blockIdx.x * blockDim.x + threadIdx.x) >> 5;
    int lane = threadIdx.x & 31;
    if (gw >= NN) return;
    const float* row = h1 + (size_t)gw * 256;
    float accl[NHEAD], accr[NHEAD];
#pragma unroll
    for (int h = 0; h < NHEAD; h++) { accl[h] = 0.f; accr[h] = 0.f; }
#pragma unroll
    for (int i = 0; i < 8; i++) {
        int j = lane + 32 * i;
        float v = row[j];
#pragma unroll
        for (int h = 0; h < NHEAD; h++) {
            accl[h] += v * g_wl2[h * 256 + j];
            accr[h] += v * g_wr2[h * 256 + j];
        }
    }
#pragma unroll
    for (int h = 0; h < NHEAD; h++) {
        float l = accl[h], r = accr[h];
#pragma unroll
        for (int o = 16; o > 0; o >>= 1) {
            l += __shfl_xor_sync(0xffffffffu, l, o);
            r += __shfl_xor_sync(0xffffffffu, r, o);
        }
        if (lane == 0) {
            g_el[gw * NHEAD + h] = l;
            g_er[gw * NHEAD + h] = r;
        }
    }
}

// ---------------- fused segment-softmax + aggregation ----------------
__device__ __forceinline__ float4 edge_score(int s, const float4& er) {
    float4 l = *reinterpret_cast<const float4*>(&g_el[s * 4]);
    float4 v;
    float x;
    x = l.x + er.x; v.x = x > 0.f ? x : 0.2f * x;
    x = l.y + er.y; v.y = x > 0.f ? x : 0.2f * x;
    x = l.z + er.z; v.z = x > 0.f ? x : 0.2f * x;
    x = l.w + er.w; v.w = x > 0.f ? x : 0.2f * x;
    return v;
}

// computes per-node softmax stats (m, inv) into m[]/inv[] registers; warp-collective
__device__ __forceinline__ void softmax_stats(int n, int j0, int j1, int lane,
                                              const float4& er, float* m, float* inv) {
    float s[NHEAD];
#pragma unroll
    for (int h = 0; h < NHEAD; h++) { m[h] = -FLT_MAX; s[h] = 0.f; }
    for (int j = j0 + lane; j < j1; j += 32) {
        float4 e4 = edge_score(g_ss[j], er);
        float ev[4] = {e4.x, e4.y, e4.z, e4.w};
#pragma unroll
        for (int h = 0; h < NHEAD; h++) {
            float nm = fmaxf(m[h], ev[h]);
            s[h] = s[h] * __expf(m[h] - nm) + __expf(ev[h] - nm);
            m[h] = nm;
        }
    }
#pragma unroll
    for (int h = 0; h < NHEAD; h++) {
#pragma unroll
        for (int o = 16; o > 0; o >>= 1) {
            float om = __shfl_xor_sync(0xffffffffu, m[h], o);
            float os = __shfl_xor_sync(0xffffffffu, s[h], o);
            float nm = fmaxf(m[h], om);
            s[h] = s[h] * __expf(m[h] - nm) + os * __expf(om - nm);
            m[h] = nm;
        }
    }
#pragma unroll
    for (int h = 0; h < NHEAD; h++) inv[h] = 1.f / fmaxf(s[h], 1e-9f);
}

// hidden layers: softmax + aggregate z (F=64/head) + bias + ELU + bf16 split
__global__ void k_softagg_mid(const float* __restrict__ z, const float* __restrict__ bias,
                              float* __restrict__ hout) {
    int n = (blockIdx.x * blockDim.x + threadIdx.x) >> 5;
    int lane = threadIdx.x & 31;
    if (n >= NN) return;
    int j0 = g_off[n], j1 = g_off[n + 1];
    float4 er = *reinterpret_cast<const float4*>(&g_er[n * 4]);
    float m[NHEAD], inv[NHEAD];
    softmax_stats(n, j0, j1, lane, er, m, inv);

    float acc[NHEAD][2];
#pragma unroll
    for (int h = 0; h < NHEAD; h++) { acc[h][0] = 0.f; acc[h][1] = 0.f; }
    for (int j = j0; j < j1; j++) {
        int sidx = g_ss[j];
        float4 e4 = edge_score(sidx, er);
        float a[4];
        a[0] = __expf(e4.x - m[0]) * inv[0];
        a[1] = __expf(e4.y - m[1]) * inv[1];
        a[2] = __expf(e4.z - m[2]) * inv[2];
        a[3] = __expf(e4.w - m[3]) * inv[3];
        const float* zr = z + (size_t)sidx * 256;
#pragma unroll
        for (int h = 0; h < NHEAD; h++) {
            acc[h][0] += a[h] * zr[h * 64 + lane];
            acc[h][1] += a[h] * zr[h * 64 + lane + 32];
        }
    }
#pragma unroll
    for (int h = 0; h < NHEAD; h++) {
        float v0 = acc[h][0] + bias[h * 64 + lane];
        float v1 = acc[h][1] + bias[h * 64 + lane + 32];
        v0 = v0 > 0.f ? v0 : (__expf(v0) - 1.f);
        v1 = v1 > 0.f ? v1 : (__expf(v1) - 1.f);
        size_t i0 = (size_t)n * 256 + h * 64 + lane;
        hout[i0] = v0;
        hout[i0 + 32] = v1;
        __nv_bfloat16 h0 = __float2bfloat16(v0);
        __nv_bfloat16 h1b = __float2bfloat16(v1);
        g_ahi[i0] = h0;
        g_ahi[i0 + 32] = h1b;
        g_alo[i0] = __float2bfloat16(v0 - __bfloat162float(h0));
        g_alo[i0 + 32] = __float2bfloat16(v1 - __bfloat162float(h1b));
    }
}

// layer 2: softmax + aggregate h1 (256-dim) into bf16 split A [N,1024]
__global__ void k_softagg2(const float* __restrict__ h1) {
    int n = (blockIdx.x * blockDim.x + threadIdx.x) >> 5;
    int lane = threadIdx.x & 31;
    if (n >= NN) return;
    int j0 = g_off[n], j1 = g_off[n + 1];
    float4 er = *reinterpret_cast<const float4*>(&g_er[n * 4]);
    float m[NHEAD], inv[NHEAD];
    softmax_stats(n, j0, j1, lane, er, m, inv);

    float acc[NHEAD][8];
#pragma unroll
    for (int h = 0; h < NHEAD; h++)
#pragma unroll
        for (int p = 0; p < 8; p++) acc[h][p] = 0.f;
    for (int j = j0; j < j1; j++) {
        int sidx = g_ss[j];
        float4 e4 = edge_score(sidx, er);
        float a[4];
        a[0] = __expf(e4.x - m[0]) * inv[0];
        a[1] = __expf(e4.y - m[1]) * inv[1];
        a[2] = __expf(e4.z - m[2]) * inv[2];
        a[3] = __expf(e4.w - m[3]) * inv[3];
        const float* hr = h1 + (size_t)sidx * 256;
#pragma unroll
        for (int p = 0; p < 8; p++) {
            float v = hr[lane + 32 * p];
            acc[0][p] += a[0] * v;
            acc[1][p] += a[1] * v;
            acc[2][p] += a[2] * v;
            acc[3][p] += a[3] * v;
        }
    }
    size_t base = (size_t)n * 1024;
#pragma unroll
    for (int h = 0; h < NHEAD; h++)
#pragma unroll
        for (int p = 0; p < 8; p++) {
            float v = acc[h][p];
            size_t idx = base + h * 256 + lane + 32 * p;
            __nv_bfloat16 hi = __float2bfloat16(v);
            g_ahi[idx] = hi;
            g_alo[idx] = __float2bfloat16(v - __bfloat162float(hi));
        }
}

// ---------------- launch ----------------
extern "C" void kernel_launch(void* const* d_in, const int* in_sizes, int n_in,
                              void* d_out, int out_size) {
    const float* feat = (const float*)d_in[0];
    const float* W0 = (const float*)d_in[1];
    const float* al0 = (const float*)d_in[2];
    const float* ar0 = (const float*)d_in[3];
    const float* b0 = (const float*)d_in[4];
    const float* W1 = (const float*)d_in[5];
    const float* al1 = (const float*)d_in[6];
    const float* ar1 = (const float*)d_in[7];
    const float* b1 = (const float*)d_in[8];
    const float* W2 = (const float*)d_in[9];
    const float* al2 = (const float*)d_in[10];
    const float* ar2 = (const float*)d_in[11];
    const float* b2 = (const float*)d_in[12];
    const int* src = (const int*)d_in[13];
    const int* dst = (const int*)d_in[14];
    float* out = (float*)d_out;

    float *p_z, *p_h, *p_bias2;
    __nv_bfloat16 *p_ahi, *p_alo, *p_bthi, *p_btlo;
    cudaGetSymbolAddress((void**)&p_z, g_z);
    cudaGetSymbolAddress((void**)&p_h, g_h);
    cudaGetSymbolAddress((void**)&p_bias2, g_bias2);
    cudaGetSymbolAddress((void**)&p_ahi, g_ahi);
    cudaGetSymbolAddress((void**)&p_alo, g_alo);
    cudaGetSymbolAddress((void**)&p_bthi, g_bthi);
    cudaGetSymbolAddress((void**)&p_btlo, g_btlo);

    const int TB = 256;
    int eb = (NE + TB - 1) / TB;
    int nwb = (NN * 32 + TB - 1) / TB;   // one warp per node
    dim3 ggrid(2, (NN + 127) / 128);

    // CSR build + weight precompute
    k_zero_deg<<<(NN + TB - 1) / TB, TB>>>();
    k_count<<<eb, TB>>>(dst);
    k_prep_scores<<<9, 256>>>(W2, al2, ar2, b2);
    k_scan<<<1, 1024>>>();
    k_fill<<<eb, TB>>>(src, dst);

    // ---- layer 0: 128 -> 4x64, ELU
    k_splitA<<<(NN * 128 + TB - 1) / TB, TB>>>(feat, p_ahi, p_alo, NN * 128);
    k_splitWt<<<(128 * 256 + TB - 1) / TB, TB>>>(W0, 128, 256);
    k_gemm_mma<<<ggrid, 256>>>(p_ahi, p_alo, p_bthi, p_btlo, p_z, NN, 256, 128, 1.f, nullptr);
    k_scores<<<nwb, TB>>>(p_z, al0, ar0);
    k_softagg_mid<<<nwb, TB>>>(p_z, b0, p_h);

    // ---- layer 1: 256 -> 4x64, ELU
    k_splitWt<<<(256 * 256 + TB - 1) / TB, TB>>>(W1, 256, 256);
    k_gemm_mma<<<ggrid, 256>>>(p_ahi, p_alo, p_bthi, p_btlo, p_z, NN, 256, 256, 1.f, nullptr);
    k_scores<<<nwb, TB>>>(p_z, al1, ar1);
    k_softagg_mid<<<nwb, TB>>>(p_z, b1, p_h);

    // ---- layer 2: scores from h1, softmax+aggregate h1, single GEMM K=1024
    k_scores2<<<nwb, TB>>>(p_h);
    k_softagg2<<<nwb, TB>>>(p_h);
    k_splitW2<<<(256 * 1024 + TB - 1) / TB, TB>>>(W2);
    k_gemm_mma<<<ggrid, 256>>>(p_ahi, p_alo, p_bthi, p_btlo, out, NN, 256, 1024, 0.25f, p_bias2);
}

// round 9
// speedup vs baseline: 1.0525x; 1.0525x over previous
#include <cuda_runtime.h>
#include <cuda_bf16.h>
#include <math.h>
#include <float.h>
#include <stdint.h>

#define NN 50000
#define NE 800000
#define NHEAD 4

// ---------------- scratch (device globals; no allocation allowed) ----------------
__device__ float g_z[(size_t)NN * 256];    // GEMM0/1 output (projected feats, fp32)
__device__ float g_h[(size_t)NN * 256];    // hidden activations (fp32, for scores/agg)
__device__ __nv_bfloat16 g_ahi[(size_t)NN * 1024];  // GEMM A operand, bf16 high part
__device__ __nv_bfloat16 g_alo[(size_t)NN * 1024];  // GEMM A operand, bf16 low part
__device__ __nv_bfloat16 g_bthi[256 * 1024];        // GEMM B operand [N,K] K-major, hi
__device__ __nv_bfloat16 g_btlo[256 * 1024];        // GEMM B operand [N,K] K-major, lo
__device__ float g_el[NN * NHEAD];
__device__ float g_er[NN * NHEAD];
__device__ int   g_ss[NE];                     // src node per sorted edge
__device__ int   g_deg[NN];
__device__ int   g_cur[NN];
__device__ int   g_off[NN + 1];
__device__ int   g_bsum[64];                   // per-block chunk sums for the scan
__device__ float g_wl2[NHEAD * 256];
__device__ float g_wr2[NHEAD * 256];
__device__ float g_bias2[256];

// ================= warp-MMA helpers (sm_80+ PTX, works under compute_103) =================
__device__ __forceinline__ uint32_t smem_u32(const void* p) {
    uint32_t a;
    asm("{ .reg .u64 t; cvta.to.shared.u64 t, %1; cvt.u32.u64 %0, t; }" : "=r"(a) : "l"(p));
    return a;
}
#define LDM4(r0, r1, r2, r3, addr) \
    asm volatile("ldmatrix.sync.aligned.m8n8.x4.shared.b16 {%0,%1,%2,%3}, [%4];" \
                 : "=r"(r0), "=r"(r1), "=r"(r2), "=r"(r3) : "r"(addr))
#define MMA16816(d, a, b) \
    asm volatile("mma.sync.aligned.m16n8k16.row.col.f32.bf16.bf16.f32 " \
                 "{%0,%1,%2,%3}, {%4,%5,%6,%7}, {%8,%9}, {%0,%1,%2,%3};" \
                 : "+f"((d)[0]), "+f"((d)[1]), "+f"((d)[2]), "+f"((d)[3]) \
                 : "r"((a)[0]), "r"((a)[1]), "r"((a)[2]), "r"((a)[3]), \
                   "r"((b)[0]), "r"((b)[1]))

// ================= split-bf16 tensor-core GEMM, register-prefetch double buffer =================
// (unchanged from R7 — proven fastest)
#define GBM 128
#define GBN 128
#define GBK 32
#define GPAD 40

__global__ void __launch_bounds__(256)
k_gemm_mma(const __nv_bfloat16* __restrict__ Ahi, const __nv_bfloat16* __restrict__ Alo,
           const __nv_bfloat16* __restrict__ Bhi, const __nv_bfloat16* __restrict__ Blo,
           float* __restrict__ C, int M, int N, int K,
           float scale, const float* __restrict__ bias) {
    __shared__ __nv_bfloat16 sAhi[GBM * GPAD];
    __shared__ __nv_bfloat16 sAlo[GBM * GPAD];
    __shared__ __nv_bfloat16 sBhi[GBN * GPAD];
    __shared__ __nv_bfloat16 sBlo[GBN * GPAD];

    int tid = threadIdx.x;
    int lane = tid & 31;
    int wid = tid >> 5;
    int wm = wid >> 2;
    int wn = wid & 3;
    int bm = blockIdx.y * GBM;
    int bn = blockIdx.x * GBN;

    uint32_t bAhi = smem_u32(sAhi), bAlo = smem_u32(sAlo);
    uint32_t bBhi = smem_u32(sBhi), bBlo = smem_u32(sBlo);

    const __nv_bfloat16* gptr[8];
    __nv_bfloat16* sptr[8];
    bool valid[8];
#pragma unroll
    for (int t = 0; t < 8; t++) {
        int idx = tid + t * 256;
        int tile = idx >> 9;
        int u = idx & 511;
        int row = u >> 2;
        int ch = u & 3;
        __nv_bfloat16* sbase = (tile == 0) ? sAhi : (tile == 1) ? sAlo : (tile == 2) ? sBhi : sBlo;
        sptr[t] = sbase + row * GPAD + ch * 8;
        if (tile < 2) {
            int gm = bm + row;
            valid[t] = (gm < M);
            const __nv_bfloat16* gb = (tile == 0) ? Ahi : Alo;
            gptr[t] = gb + (size_t)(valid[t] ? gm : 0) * K + ch * 8;
        } else {
            int gn = bn + row;
            valid[t] = true;
            const __nv_bfloat16* gb = (tile == 2) ? Bhi : Blo;
            gptr[t] = gb + (size_t)gn * K + ch * 8;
        }
    }

    float acc[4][4][4];
#pragma unroll
    for (int i = 0; i < 4; i++)
#pragma unroll
        for (int j = 0; j < 4; j++)
#pragma unroll
            for (int r = 0; r < 4; r++) acc[i][j][r] = 0.f;

    int lrow = lane & 15;
    int lcol = (lane >> 4) * 8;

    int nst = K / GBK;
    uint4 pre[8];
#pragma unroll
    for (int t = 0; t < 8; t++)
        pre[t] = valid[t] ? *reinterpret_cast<const uint4*>(gptr[t]) : make_uint4(0, 0, 0, 0);

    for (int s = 0; s < nst; s++) {
#pragma unroll
        for (int t = 0; t < 8; t++) *reinterpret_cast<uint4*>(sptr[t]) = pre[t];
        __syncthreads();

        if (s + 1 < nst) {
            int k0 = (s + 1) * GBK;
#pragma unroll
            for (int t = 0; t < 8; t++)
                pre[t] = valid[t] ? *reinterpret_cast<const uint4*>(gptr[t] + k0)
                                  : make_uint4(0, 0, 0, 0);
        }

#pragma unroll
        for (int kk = 0; kk < 2; kk++) {
            int kb = kk * 16;
            uint32_t ahi[4][4], alo[4][4];
#pragma unroll
            for (int i = 0; i < 4; i++) {
                uint32_t off = (uint32_t)((wm * 64 + i * 16 + lrow) * GPAD + kb + lcol) * 2;
                LDM4(ahi[i][0], ahi[i][1], ahi[i][2], ahi[i][3], bAhi + off);
                LDM4(alo[i][0], alo[i][1], alo[i][2], alo[i][3], bAlo + off);
            }
            uint32_t bhi[4][2], blo[4][2];
#pragma unroll
            for (int j = 0; j < 2; j++) {
                uint32_t off = (uint32_t)((wn * 32 + j * 16 + lrow) * GPAD + kb + lcol) * 2;
                uint32_t r0, r1, r2, r3;
                LDM4(r0, r1, r2, r3, bBhi + off);
                bhi[2 * j][0] = r0; bhi[2 * j][1] = r2;
                bhi[2 * j + 1][0] = r1; bhi[2 * j + 1][1] = r3;
                LDM4(r0, r1, r2, r3, bBlo + off);
                blo[2 * j][0] = r0; blo[2 * j][1] = r2;
                blo[2 * j + 1][0] = r1; blo[2 * j + 1][1] = r3;
            }
#pragma unroll
            for (int i = 0; i < 4; i++)
#pragma unroll
                for (int n = 0; n < 4; n++) {
                    MMA16816(acc[i][n], ahi[i], bhi[n]);
                    MMA16816(acc[i][n], ahi[i], blo[n]);
                    MMA16816(acc[i][n], alo[i], bhi[n]);
                }
        }
        __syncthreads();
    }

    int g = lane >> 2, tg = lane & 3;
#pragma unroll
    for (int mi = 0; mi < 4; mi++) {
        int r0 = bm + wm * 64 + mi * 16 + g;
        int r1 = r0 + 8;
#pragma unroll
        for (int ni = 0; ni < 4; ni++) {
            int c = bn + wn * 32 + ni * 8 + tg * 2;
            float b0 = 0.f, b1 = 0.f;
            if (bias) { b0 = bias[c]; b1 = bias[c + 1]; }
            if (r0 < M) {
                float2 v = make_float2(scale * acc[mi][ni][0] + b0,
                                       scale * acc[mi][ni][1] + b1);
                *reinterpret_cast<float2*>(&C[(size_t)r0 * N + c]) = v;
            }
            if (r1 < M) {
                float2 v = make_float2(scale * acc[mi][ni][2] + b0,
                                       scale * acc[mi][ni][3] + b1);
                *reinterpret_cast<float2*>(&C[(size_t)r1 * N + c]) = v;
            }
        }
    }
}

// ================= bf16 split conversions =================
__global__ void k_splitA(const float* __restrict__ in, __nv_bfloat16* __restrict__ hi,
                         __nv_bfloat16* __restrict__ lo, int count) {
    int i = blockIdx.x * blockDim.x + threadIdx.x;
    if (i >= count) return;
    float f = in[i];
    __nv_bfloat16 h = __float2bfloat16(f);
    hi[i] = h;
    lo[i] = __float2bfloat16(f - __bfloat162float(h));
}

__global__ void k_splitWt(const float* __restrict__ W, int K, int N) {
    int t = blockIdx.x * blockDim.x + threadIdx.x;
    if (t >= K * N) return;
    int n = t / K, k = t % K;
    float f = W[(size_t)k * N + n];
    __nv_bfloat16 h = __float2bfloat16(f);
    g_bthi[t] = h;
    g_btlo[t] = __float2bfloat16(f - __bfloat162float(h));
}

__global__ void k_splitW2(const float* __restrict__ W2) {
    int t = blockIdx.x * blockDim.x + threadIdx.x;
    if (t >= 256 * 1024) return;
    int c = t >> 10;
    int r = t & 1023;
    int h = r >> 8, kk = r & 255;
    float f = W2[(size_t)kk * 1024 + h * 256 + c];
    __nv_bfloat16 hh = __float2bfloat16(f);
    g_bthi[t] = hh;
    g_btlo[t] = __float2bfloat16(f - __bfloat162float(hh));
}

// ---------------- CSR build (by destination) ----------------
__global__ void k_count(const int* __restrict__ dst) {
    int i = blockIdx.x * blockDim.x + threadIdx.x;
    if (i < NE) atomicAdd(&g_deg[dst[i]], 1);
}

// scan stage 1: 49 parallel blocks, per-block exclusive scan + block totals
__global__ void k_scan1() {
    __shared__ int warpsum[32];
    int b = blockIdx.x, tid = threadIdx.x;
    int lane = tid & 31, wrp = tid >> 5;
    int i = b * 1024 + tid;
    int v = (i < NN) ? g_deg[i] : 0;
    int x = v;
#pragma unroll
    for (int o = 1; o < 32; o <<= 1) {
        int t = __shfl_up_sync(0xffffffffu, x, o);
        if (lane >= o) x += t;
    }
    if (lane == 31) warpsum[wrp] = x;
    __syncthreads();
    if (wrp == 0) {
        int w = warpsum[lane];
#pragma unroll
        for (int o = 1; o < 32; o <<= 1) {
            int t = __shfl_up_sync(0xffffffffu, w, o);
            if (lane >= o) w += t;
        }
        warpsum[lane] = w;
    }
    __syncthreads();
    int excl = (wrp ? warpsum[wrp - 1] : 0) + x - v;
    if (i < NN) g_off[i] = excl;          // block-local exclusive; global offset added in stage 2
    if (tid == 0) g_bsum[b] = warpsum[31];
}

// scan stage 2: each block re-derives its global offset from the <=48 block sums
__global__ void k_scan2() {
    __shared__ int boff_s;
    int b = blockIdx.x, tid = threadIdx.x;
    if (tid == 0) boff_s = 0;
    __syncthreads();
    if (tid < b) atomicAdd(&boff_s, g_bsum[tid]);   // exact integer adds, order-independent
    __syncthreads();
    int boff = boff_s;
    int i = b * 1024 + tid;
    if (i < NN) {
        int o = g_off[i] + boff;
        g_off[i] = o;
        g_cur[i] = o;
    }
    if (b == gridDim.x - 1 && tid == 0) g_off[NN] = boff + g_bsum[b];
}

__global__ void k_fill(const int* __restrict__ src, const int* __restrict__ dst) {
    int i = blockIdx.x * blockDim.x + threadIdx.x;
    if (i < NE) {
        int d = dst[i];
        int p = atomicAdd(&g_cur[d], 1);
        g_ss[p] = src[i];
    }
}

// ---------------- fused: zero g_deg + layer-2 wl2/wr2 + bias2 ----------------
__global__ void k_prep(const float* __restrict__ W2, const float* __restrict__ al2,
                       const float* __restrict__ ar2, const float* __restrict__ b2) {
    int t = blockIdx.x * blockDim.x + threadIdx.x;
    if (t < NN) g_deg[t] = 0;
    int u = t - NN;
    if (u >= 0 && u < 2048) {
        int which = u >> 10;
        int hk = u & 1023;
        int h = hk >> 8, k = hk & 255;
        const float* a = (which == 0 ? al2 : ar2) + h * 256;
        const float* wrow = W2 + (size_t)k * 1024 + h * 256;
        float s = 0.f;
#pragma unroll 8
        for (int c = 0; c < 256; c++) s += wrow[c] * a[c];
        if (which == 0) g_wl2[hk] = s;
        else            g_wr2[hk] = s;
    } else if (u >= 2048 && u < 2304) {
        int c = u - 2048;
        g_bias2[c] = 0.25f * (b2[c] + b2[256 + c] + b2[512 + c] + b2[768 + c]);
    }
}

// ---------------- per-node attention scores (layers 0/1, F=64) ----------------
__global__ void k_scores(const float* __restrict__ z, const float* __restrict__ al,
                         const float* __restrict__ ar) {
    int gw = (blockIdx.x * blockDim.x + threadIdx.x) >> 5;
    int lane = threadIdx.x & 31;
    if (gw >= NN) return;
    const float* row = z + (size_t)gw * 256;
    float accl[NHEAD], accr[NHEAD];
#pragma unroll
    for (int h = 0; h < NHEAD; h++) { accl[h] = 0.f; accr[h] = 0.f; }
#pragma unroll
    for (int i = 0; i < 8; i++) {
        int j = lane + 32 * i;
        float v = row[j];
        int h = i >> 1;
        accl[h] += v * al[j];
        accr[h] += v * ar[j];
    }
#pragma unroll
    for (int h = 0; h < NHEAD; h++) {
        float l = accl[h], r = accr[h];
#pragma unroll
        for (int o = 16; o > 0; o >>= 1) {
            l += __shfl_xor_sync(0xffffffffu, l, o);
            r += __shfl_xor_sync(0xffffffffu, r, o);
        }
        if (lane == 0) {
            g_el[gw * NHEAD + h] = l;
            g_er[gw * NHEAD + h] = r;
        }
    }
}

// ---------------- layer-2 scores directly from h1 ----------------
__global__ void k_scores2(const float* __restrict__ h1) {
    int gw = (blockIdx.x * blockDim.x + threadIdx.x) >> 5;
    int lane = threadIdx.x & 31;
    if (gw >= NN) return;
    const float* row = h1 + (size_t)gw * 256;
    float accl[NHEAD], accr[NHEAD];
#pragma unroll
    for (int h = 0; h < NHEAD; h++) { accl[h] = 0.f; accr[h] = 0.f; }
#pragma unroll
    for (int i = 0; i < 8; i++) {
        int j = lane + 32 * i;
        float v = row[j];
#pragma unroll
        for (int h = 0; h < NHEAD; h++) {
            accl[h] += v * g_wl2[h * 256 + j];
            accr[h] += v * g_wr2[h * 256 + j];
        }
    }
#pragma unroll
    for (int h = 0; h < NHEAD; h++) {
        float l = accl[h], r = accr[h];
#pragma unroll
        for (int o = 16; o > 0; o >>= 1) {
            l += __shfl_xor_sync(0xffffffffu, l, o);
            r += __shfl_xor_sync(0xffffffffu, r, o);
        }
        if (lane == 0) {
            g_el[gw * NHEAD + h] = l;
            g_er[gw * NHEAD + h] = r;
        }
    }
}

// ---------------- fused segment-softmax + aggregation ----------------
__device__ __forceinline__ float4 edge_score(int s, const float4& er) {
    float4 l = *reinterpret_cast<const float4*>(&g_el[s * 4]);
    float4 v;
    float x;
    x = l.x + er.x; v.x = x > 0.f ? x : 0.2f * x;
    x = l.y + er.y; v.y = x > 0.f ? x : 0.2f * x;
    x = l.z + er.z; v.z = x > 0.f ? x : 0.2f * x;
    x = l.w + er.w; v.w = x > 0.f ? x : 0.2f * x;
    return v;
}

__device__ __forceinline__ void softmax_stats(int n, int j0, int j1, int lane,
                                              const float4& er, float* m, float* inv) {
    float s[NHEAD];
#pragma unroll
    for (int h = 0; h < NHEAD; h++) { m[h] = -FLT_MAX; s[h] = 0.f; }
    for (int j = j0 + lane; j < j1; j += 32) {
        float4 e4 = edge_score(g_ss[j], er);
        float ev[4] = {e4.x, e4.y, e4.z, e4.w};
#pragma unroll
        for (int h = 0; h < NHEAD; h++) {
            float nm = fmaxf(m[h], ev[h]);
            s[h] = s[h] * __expf(m[h] - nm) + __expf(ev[h] - nm);
            m[h] = nm;
        }
    }
#pragma unroll
    for (int h = 0; h < NHEAD; h++) {
#pragma unroll
        for (int o = 16; o > 0; o >>= 1) {
            float om = __shfl_xor_sync(0xffffffffu, m[h], o);
            float os = __shfl_xor_sync(0xffffffffu, s[h], o);
            float nm = fmaxf(m[h], om);
            s[h] = s[h] * __expf(m[h] - nm) + os * __expf(om - nm);
            m[h] = nm;
        }
    }
#pragma unroll
    for (int h = 0; h < NHEAD; h++) inv[h] = 1.f / fmaxf(s[h], 1e-9f);
}

__global__ void k_softagg_mid(const float* __restrict__ z, const float* __restrict__ bias,
                              float* __restrict__ hout) {
    int n = (blockIdx.x * blockDim.x + threadIdx.x) >> 5;
    int lane = threadIdx.x & 31;
    if (n >= NN) return;
    int j0 = g_off[n], j1 = g_off[n + 1];
    float4 er = *reinterpret_cast<const float4*>(&g_er[n * 4]);
    float m[NHEAD], inv[NHEAD];
    softmax_stats(n, j0, j1, lane, er, m, inv);

    float acc[NHEAD][2];
#pragma unroll
    for (int h = 0; h < NHEAD; h++) { acc[h][0] = 0.f; acc[h][1] = 0.f; }
    for (int j = j0; j < j1; j++) {
        int sidx = g_ss[j];
        float4 e4 = edge_score(sidx, er);
        float a[4];
        a[0] = __expf(e4.x - m[0]) * inv[0];
        a[1] = __expf(e4.y - m[1]) * inv[1];
        a[2] = __expf(e4.z - m[2]) * inv[2];
        a[3] = __expf(e4.w - m[3]) * inv[3];
        const float* zr = z + (size_t)sidx * 256;
#pragma unroll
        for (int h = 0; h < NHEAD; h++) {
            acc[h][0] += a[h] * zr[h * 64 + lane];
            acc[h][1] += a[h] * zr[h * 64 + lane + 32];
        }
    }
#pragma unroll
    for (int h = 0; h < NHEAD; h++) {
        float v0 = acc[h][0] + bias[h * 64 + lane];
        float v1 = acc[h][1] + bias[h * 64 + lane + 32];
        v0 = v0 > 0.f ? v0 : (__expf(v0) - 1.f);
        v1 = v1 > 0.f ? v1 : (__expf(v1) - 1.f);
        size_t i0 = (size_t)n * 256 + h * 64 + lane;
        hout[i0] = v0;
        hout[i0 + 32] = v1;
        __nv_bfloat16 h0 = __float2bfloat16(v0);
        __nv_bfloat16 h1b = __float2bfloat16(v1);
        g_ahi[i0] = h0;
        g_ahi[i0 + 32] = h1b;
        g_alo[i0] = __float2bfloat16(v0 - __bfloat162float(h0));
        g_alo[i0 + 32] = __float2bfloat16(v1 - __bfloat162float(h1b));
    }
}

__global__ void k_softagg2(const float* __restrict__ h1) {
    int n = (blockIdx.x * blockDim.x + threadIdx.x) >> 5;
    int lane = threadIdx.x & 31;
    if (n >= NN) return;
    int j0 = g_off[n], j1 = g_off[n + 1];
    float4 er = *reinterpret_cast<const float4*>(&g_er[n * 4]);
    float m[NHEAD], inv[NHEAD];
    softmax_stats(n, j0, j1, lane, er, m, inv);

    float acc[NHEAD][8];
#pragma unroll
    for (int h = 0; h < NHEAD; h++)
#pragma unroll
        for (int p = 0; p < 8; p++) acc[h][p] = 0.f;
    for (int j = j0; j < j1; j++) {
        int sidx = g_ss[j];
        float4 e4 = edge_score(sidx, er);
        float a[4];
        a[0] = __expf(e4.x - m[0]) * inv[0];
        a[1] = __expf(e4.y - m[1]) * inv[1];
        a[2] = __expf(e4.z - m[2]) * inv[2];
        a[3] = __expf(e4.w - m[3]) * inv[3];
        const float* hr = h1 + (size_t)sidx * 256;
#pragma unroll
        for (int p = 0; p < 8; p++) {
            float v = hr[lane + 32 * p];
            acc[0][p] += a[0] * v;
            acc[1][p] += a[1] * v;
            acc[2][p] += a[2] * v;
            acc[3][p] += a[3] * v;
        }
    }
    size_t base = (size_t)n * 1024;
#pragma unroll
    for (int h = 0; h < NHEAD; h++)
#pragma unroll
        for (int p = 0; p < 8; p++) {
            float v = acc[h][p];
            size_t idx = base + h * 256 + lane + 32 * p;
            __nv_bfloat16 hi = __float2bfloat16(v);
            g_ahi[idx] = hi;
            g_alo[idx] = __float2bfloat16(v - __bfloat162float(hi));
        }
}

// ---------------- launch ----------------
extern "C" void kernel_launch(void* const* d_in, const int* in_sizes, int n_in,
                              void* d_out, int out_size) {
    const float* feat = (const float*)d_in[0];
    const float* W0 = (const float*)d_in[1];
    const float* al0 = (const float*)d_in[2];
    const float* ar0 = (const float*)d_in[3];
    const float* b0 = (const float*)d_in[4];
    const float* W1 = (const float*)d_in[5];
    const float* al1 = (const float*)d_in[6];
    const float* ar1 = (const float*)d_in[7];
    const float* b1 = (const float*)d_in[8];
    const float* W2 = (const float*)d_in[9];
    const float* al2 = (const float*)d_in[10];
    const float* ar2 = (const float*)d_in[11];
    const float* b2 = (const float*)d_in[12];
    const int* src = (const int*)d_in[13];
    const int* dst = (const int*)d_in[14];
    float* out = (float*)d_out;

    float *p_z, *p_h, *p_bias2;
    __nv_bfloat16 *p_ahi, *p_alo, *p_bthi, *p_btlo;
    cudaGetSymbolAddress((void**)&p_z, g_z);
    cudaGetSymbolAddress((void**)&p_h, g_h);
    cudaGetSymbolAddress((void**)&p_bias2, g_bias2);
    cudaGetSymbolAddress((void**)&p_ahi, g_ahi);
    cudaGetSymbolAddress((void**)&p_alo, g_alo);
    cudaGetSymbolAddress((void**)&p_bthi, g_bthi);
    cudaGetSymbolAddress((void**)&p_btlo, g_btlo);

    const int TB = 256;
    int eb = (NE + TB - 1) / TB;
    int nwb = (NN * 32 + TB - 1) / TB;   // one warp per node
    int scb = (NN + 1023) / 1024;        // 49 scan blocks
    dim3 ggrid(2, (NN + 127) / 128);

    // CSR build + weight precompute
    k_prep<<<(NN + 2304 + TB - 1) / TB, TB>>>(W2, al2, ar2, b2);  // zero g_deg + wl2/wr2/bias2
    k_count<<<eb, TB>>>(dst);
    k_scan1<<<scb, 1024>>>();
    k_scan2<<<scb, 1024>>>();
    k_fill<<<eb, TB>>>(src, dst);

    // ---- layer 0: 128 -> 4x64, ELU
    k_splitA<<<(NN * 128 + TB - 1) / TB, TB>>>(feat, p_ahi, p_alo, NN * 128);
    k_splitWt<<<(128 * 256 + TB - 1) / TB, TB>>>(W0, 128, 256);
    k_gemm_mma<<<ggrid, 256>>>(p_ahi, p_alo, p_bthi, p_btlo, p_z, NN, 256, 128, 1.f, nullptr);
    k_scores<<<nwb, TB>>>(p_z, al0, ar0);
    k_softagg_mid<<<nwb, TB>>>(p_z, b0, p_h);

    // ---- layer 1: 256 -> 4x64, ELU
    k_splitWt<<<(256 * 256 + TB - 1) / TB, TB>>>(W1, 256, 256);
    k_gemm_mma<<<ggrid, 256>>>(p_ahi, p_alo, p_bthi, p_btlo, p_z, NN, 256, 256, 1.f, nullptr);
    k_scores<<<nwb, TB>>>(p_z, al1, ar1);
    k_softagg_mid<<<nwb, TB>>>(p_z, b1, p_h);

    // ---- layer 2: scores from h1, softmax+aggregate h1, single GEMM K=1024
    k_scores2<<<nwb, TB>>>(p_h);
    k_softagg2<<<nwb, TB>>>(p_h);
    k_splitW2<<<(256 * 1024 + TB - 1) / TB, TB>>>(W2);
    k_gemm_mma<<<ggrid, 256>>>(p_ahi, p_alo, p_bthi, p_btlo, out, NN, 256, 1024, 0.25f, p_bias2);
}

// round 14
// speedup vs baseline: 1.0817x; 1.0277x over previous
#include <cuda_runtime.h>
#include <cuda_bf16.h>
#include <math.h>
#include <float.h>
#include <stdint.h>

#define NN 50000
#define NE 800000
#define NHEAD 4

// ---------------- scratch (device globals; no allocation allowed) ----------------
__device__ float g_z[(size_t)NN * 256];    // GEMM0/1 output (projected feats, fp32)
__device__ float g_h[(size_t)NN * 256];    // hidden activations (fp32, for scores/agg)
__device__ __nv_bfloat16 g_ahi[(size_t)NN * 1024];  // GEMM A operand, bf16 high part
__device__ __nv_bfloat16 g_alo[(size_t)NN * 1024];  // GEMM A operand, bf16 low part
__device__ __nv_bfloat16 g_b0hi[256 * 128], g_b0lo[256 * 128];   // W0^T split
__device__ __nv_bfloat16 g_b1hi[256 * 256], g_b1lo[256 * 256];   // W1^T split
__device__ __nv_bfloat16 g_b2hi[256 * 1024], g_b2lo[256 * 1024]; // W2 permuted split
__device__ float g_el[NN * NHEAD];
__device__ float g_er[NN * NHEAD];
__device__ float g_el2[NN * NHEAD];   // layer-2 scores (written fused in layer-1 agg)
__device__ float g_er2[NN * NHEAD];
__device__ int   g_ss[NE];                     // src node per sorted edge
__device__ int   g_deg[NN];
__device__ int   g_cur[NN];
__device__ int   g_off[NN + 1];
__device__ int   g_bsum[64];
__device__ float g_wl2[NHEAD * 256];
__device__ float g_wr2[NHEAD * 256];
__device__ float g_bias2[256];

// ================= warp-MMA helpers (sm_80+ PTX, works under compute_103) =================
__device__ __forceinline__ uint32_t smem_u32(const void* p) {
    uint32_t a;
    asm("{ .reg .u64 t; cvta.to.shared.u64 t, %1; cvt.u32.u64 %0, t; }" : "=r"(a) : "l"(p));
    return a;
}
#define LDM4(r0, r1, r2, r3, addr) \
    asm volatile("ldmatrix.sync.aligned.m8n8.x4.shared.b16 {%0,%1,%2,%3}, [%4];" \
                 : "=r"(r0), "=r"(r1), "=r"(r2), "=r"(r3) : "r"(addr))
#define MMA16816(d, a, b) \
    asm volatile("mma.sync.aligned.m16n8k16.row.col.f32.bf16.bf16.f32 " \
                 "{%0,%1,%2,%3}, {%4,%5,%6,%7}, {%8,%9}, {%0,%1,%2,%3};" \
                 : "+f"((d)[0]), "+f"((d)[1]), "+f"((d)[2]), "+f"((d)[3]) \
                 : "r"((a)[0]), "r"((a)[1]), "r"((a)[2]), "r"((a)[3]), \
                   "r"((b)[0]), "r"((b)[1]))

// ================= split-bf16 tensor-core GEMM, register-prefetch double buffer =================
// (unchanged from R7/R9 — proven fastest)
#define GBM 128
#define GBN 128
#define GBK 32
#define GPAD 40

__global__ void __launch_bounds__(256)
k_gemm_mma(const __nv_bfloat16* __restrict__ Ahi, const __nv_bfloat16* __restrict__ Alo,
           const __nv_bfloat16* __restrict__ Bhi, const __nv_bfloat16* __restrict__ Blo,
           float* __restrict__ C, int M, int N, int K,
           float scale, const float* __restrict__ bias) {
    __shared__ __nv_bfloat16 sAhi[GBM * GPAD];
    __shared__ __nv_bfloat16 sAlo[GBM * GPAD];
    __shared__ __nv_bfloat16 sBhi[GBN * GPAD];
    __shared__ __nv_bfloat16 sBlo[GBN * GPAD];

    int tid = threadIdx.x;
    int lane = tid & 31;
    int wid = tid >> 5;
    int wm = wid >> 2;
    int wn = wid & 3;
    int bm = blockIdx.y * GBM;
    int bn = blockIdx.x * GBN;

    uint32_t bAhi = smem_u32(sAhi), bAlo = smem_u32(sAlo);
    uint32_t bBhi = smem_u32(sBhi), bBlo = smem_u32(sBlo);

    const __nv_bfloat16* gptr[8];
    __nv_bfloat16* sptr[8];
    bool valid[8];
#pragma unroll
    for (int t = 0; t < 8; t++) {
        int idx = tid + t * 256;
        int tile = idx >> 9;
        int u = idx & 511;
        int row = u >> 2;
        int ch = u & 3;
        __nv_bfloat16* sbase = (tile == 0) ? sAhi : (tile == 1) ? sAlo : (tile == 2) ? sBhi : sBlo;
        sptr[t] = sbase + row * GPAD + ch * 8;
        if (tile < 2) {
            int gm = bm + row;
            valid[t] = (gm < M);
            const __nv_bfloat16* gb = (tile == 0) ? Ahi : Alo;
            gptr[t] = gb + (size_t)(valid[t] ? gm : 0) * K + ch * 8;
        } else {
            int gn = bn + row;
            valid[t] = true;
            const __nv_bfloat16* gb = (tile == 2) ? Bhi : Blo;
            gptr[t] = gb + (size_t)gn * K + ch * 8;
        }
    }

    float acc[4][4][4];
#pragma unroll
    for (int i = 0; i < 4; i++)
#pragma unroll
        for (int j = 0; j < 4; j++)
#pragma unroll
            for (int r = 0; r < 4; r++) acc[i][j][r] = 0.f;

    int lrow = lane & 15;
    int lcol = (lane >> 4) * 8;

    int nst = K / GBK;
    uint4 pre[8];
#pragma unroll
    for (int t = 0; t < 8; t++)
        pre[t] = valid[t] ? *reinterpret_cast<const uint4*>(gptr[t]) : make_uint4(0, 0, 0, 0);

    for (int s = 0; s < nst; s++) {
#pragma unroll
        for (int t = 0; t < 8; t++) *reinterpret_cast<uint4*>(sptr[t]) = pre[t];
        __syncthreads();

        if (s + 1 < nst) {
            int k0 = (s + 1) * GBK;
#pragma unroll
            for (int t = 0; t < 8; t++)
                pre[t] = valid[t] ? *reinterpret_cast<const uint4*>(gptr[t] + k0)
                                  : make_uint4(0, 0, 0, 0);
        }

#pragma unroll
        for (int kk = 0; kk < 2; kk++) {
            int kb = kk * 16;
            uint32_t ahi[4][4], alo[4][4];
#pragma unroll
            for (int i = 0; i < 4; i++) {
                uint32_t off = (uint32_t)((wm * 64 + i * 16 + lrow) * GPAD + kb + lcol) * 2;
                LDM4(ahi[i][0], ahi[i][1], ahi[i][2], ahi[i][3], bAhi + off);
                LDM4(alo[i][0], alo[i][1], alo[i][2], alo[i][3], bAlo + off);
            }
            uint32_t bhi[4][2], blo[4][2];
#pragma unroll
            for (int j = 0; j < 2; j++) {
                uint32_t off = (uint32_t)((wn * 32 + j * 16 + lrow) * GPAD + kb + lcol) * 2;
                uint32_t r0, r1, r2, r3;
                LDM4(r0, r1, r2, r3, bBhi + off);
                bhi[2 * j][0] = r0; bhi[2 * j][1] = r2;
                bhi[2 * j + 1][0] = r1; bhi[2 * j + 1][1] = r3;
                LDM4(r0, r1, r2, r3, bBlo + off);
                blo[2 * j][0] = r0; blo[2 * j][1] = r2;
                blo[2 * j + 1][0] = r1; blo[2 * j + 1][1] = r3;
            }
#pragma unroll
            for (int i = 0; i < 4; i++)
#pragma unroll
                for (int n = 0; n < 4; n++) {
                    MMA16816(acc[i][n], ahi[i], bhi[n]);
                    MMA16816(acc[i][n], ahi[i], blo[n]);
                    MMA16816(acc[i][n], alo[i], bhi[n]);
                }
        }
        __syncthreads();
    }

    int g = lane >> 2, tg = lane & 3;
#pragma unroll
    for (int mi = 0; mi < 4; mi++) {
        int r0 = bm + wm * 64 + mi * 16 + g;
        int r1 = r0 + 8;
#pragma unroll
        for (int ni = 0; ni < 4; ni++) {
            int c = bn + wn * 32 + ni * 8 + tg * 2;
            float b0 = 0.f, b1 = 0.f;
            if (bias) { b0 = bias[c]; b1 = bias[c + 1]; }
            if (r0 < M) {
                float2 v = make_float2(scale * acc[mi][ni][0] + b0,
                                       scale * acc[mi][ni][1] + b1);
                *reinterpret_cast<float2*>(&C[(size_t)r0 * N + c]) = v;
            }
            if (r1 < M) {
                float2 v = make_float2(scale * acc[mi][ni][2] + b0,
                                       scale * acc[mi][ni][3] + b1);
                *reinterpret_cast<float2*>(&C[(size_t)r1 * N + c]) = v;
            }
        }
    }
}

// ================= mega prep: zero deg + wl2/wr2/bias2 + all weight splits =================
__device__ __forceinline__ void split1(float f, __nv_bfloat16* hi, __nv_bfloat16* lo, int i) {
    __nv_bfloat16 h = __float2bfloat16(f);
    hi[i] = h;
    lo[i] = __float2bfloat16(f - __bfloat162float(h));
}

#define PREP_W0 (NN + 2304)
#define PREP_W1 (PREP_W0 + 256 * 128)
#define PREP_W2 (PREP_W1 + 256 * 256)
#define PREP_TOT (PREP_W2 + 256 * 1024)

__global__ void k_prep(const float* __restrict__ W0, const float* __restrict__ W1,
                       const float* __restrict__ W2, const float* __restrict__ al2,
                       const float* __restrict__ ar2, const float* __restrict__ b2) {
    int t = blockIdx.x * blockDim.x + threadIdx.x;
    if (t < NN) {
        g_deg[t] = 0;
    } else if (t < NN + 2048) {
        int u = t - NN;
        int which = u >> 10;
        int hk = u & 1023;
        int h = hk >> 8, k = hk & 255;
        const float* a = (which == 0 ? al2 : ar2) + h * 256;
        const float* wrow = W2 + (size_t)k * 1024 + h * 256;
        float s = 0.f;
#pragma unroll 8
        for (int c = 0; c < 256; c++) s += wrow[c] * a[c];
        if (which == 0) g_wl2[hk] = s;
        else            g_wr2[hk] = s;
    } else if (t < PREP_W0) {
        int c = t - NN - 2048;
        g_bias2[c] = 0.25f * (b2[c] + b2[256 + c] + b2[512 + c] + b2[768 + c]);
    } else if (t < PREP_W1) {
        int idx = t - PREP_W0;           // W0^T: [256,128], Bt[n*128+k] = W0[k*256+n]
        int n = idx >> 7, k = idx & 127;
        split1(W0[(size_t)k * 256 + n], g_b0hi, g_b0lo, idx);
    } else if (t < PREP_W2) {
        int idx = t - PREP_W1;           // W1^T: [256,256]
        int n = idx >> 8, k = idx & 255;
        split1(W1[(size_t)k * 256 + n], g_b1hi, g_b1lo, idx);
    } else if (t < PREP_TOT) {
        int idx = t - PREP_W2;           // W2 permuted: out[c][h*256+kk] = W2[kk*1024+h*256+c]
        int c = idx >> 10;
        int r = idx & 1023;
        int h = r >> 8, kk = r & 255;
        split1(W2[(size_t)kk * 1024 + h * 256 + c], g_b2hi, g_b2lo, idx);
    }
}

// vectorized feat split (count multiple of 4)
__global__ void k_splitA(const float* __restrict__ in, __nv_bfloat16* __restrict__ hi,
                         __nv_bfloat16* __restrict__ lo, int count4) {
    int i = blockIdx.x * blockDim.x + threadIdx.x;
    if (i >= count4) return;
    float4 f = reinterpret_cast<const float4*>(in)[i];
    __nv_bfloat16 h0 = __float2bfloat16(f.x), h1 = __float2bfloat16(f.y);
    __nv_bfloat16 h2 = __float2bfloat16(f.z), h3 = __float2bfloat16(f.w);
    __nv_bfloat162* hp = reinterpret_cast<__nv_bfloat162*>(hi + 4 * (size_t)i);
    hp[0] = __nv_bfloat162(h0, h1);
    hp[1] = __nv_bfloat162(h2, h3);
    __nv_bfloat162* lp = reinterpret_cast<__nv_bfloat162*>(lo + 4 * (size_t)i);
    lp[0] = __nv_bfloat162(__float2bfloat16(f.x - __bfloat162float(h0)),
                           __float2bfloat16(f.y - __bfloat162float(h1)));
    lp[1] = __nv_bfloat162(__float2bfloat16(f.z - __bfloat162float(h2)),
                           __float2bfloat16(f.w - __bfloat162float(h3)));
}

// ---------------- CSR build (by destination) ----------------
__global__ void k_count(const int* __restrict__ dst) {
    int i = blockIdx.x * blockDim.x + threadIdx.x;
    if (i < NE) atomicAdd(&g_deg[dst[i]], 1);
}

__global__ void k_scan1() {
    __shared__ int warpsum[32];
    int b = blockIdx.x, tid = threadIdx.x;
    int lane = tid & 31, wrp = tid >> 5;
    int i = b * 1024 + tid;
    int v = (i < NN) ? g_deg[i] : 0;
    int x = v;
#pragma unroll
    for (int o = 1; o < 32; o <<= 1) {
        int t = __shfl_up_sync(0xffffffffu, x, o);
        if (lane >= o) x += t;
    }
    if (lane == 31) warpsum[wrp] = x;
    __syncthreads();
    if (wrp == 0) {
        int w = warpsum[lane];
#pragma unroll
        for (int o = 1; o < 32; o <<= 1) {
            int t = __shfl_up_sync(0xffffffffu, w, o);
            if (lane >= o) w += t;
        }
        warpsum[lane] = w;
    }
    __syncthreads();
    int excl = (wrp ? warpsum[wrp - 1] : 0) + x - v;
    if (i < NN) g_off[i] = excl;
    if (tid == 0) g_bsum[b] = warpsum[31];
}

__global__ void k_scan2() {
    __shared__ int boff_s;
    int b = blockIdx.x, tid = threadIdx.x;
    if (tid == 0) boff_s = 0;
    __syncthreads();
    if (tid < b) atomicAdd(&boff_s, g_bsum[tid]);
    __syncthreads();
    int boff = boff_s;
    int i = b * 1024 + tid;
    if (i < NN) {
        int o = g_off[i] + boff;
        g_off[i] = o;
        g_cur[i] = o;
    }
    if (b == gridDim.x - 1 && tid == 0) g_off[NN] = boff + g_bsum[b];
}

__global__ void k_fill(const int* __restrict__ src, const int* __restrict__ dst) {
    int i = blockIdx.x * blockDim.x + threadIdx.x;
    if (i < NE) {
        int d = dst[i];
        int p = atomicAdd(&g_cur[d], 1);
        g_ss[p] = src[i];
    }
}

// ---------------- per-node attention scores (layers 0/1, F=64) ----------------
__global__ void k_scores(const float* __restrict__ z, const float* __restrict__ al,
                         const float* __restrict__ ar) {
    int gw = (blockIdx.x * blockDim.x + threadIdx.x) >> 5;
    int lane = threadIdx.x & 31;
    if (gw >= NN) return;
    const float* row = z + (size_t)gw * 256;
    float accl[NHEAD], accr[NHEAD];
#pragma unroll
    for (int h = 0; h < NHEAD; h++) { accl[h] = 0.f; accr[h] = 0.f; }
#pragma unroll
    for (int i = 0; i < 8; i++) {
        int j = lane + 32 * i;
        float v = row[j];
        int h = i >> 1;
        accl[h] += v * al[j];
        accr[h] += v * ar[j];
    }
#pragma unroll
    for (int h = 0; h < NHEAD; h++) {
        float l = accl[h], r = accr[h];
#pragma unroll
        for (int o = 16; o > 0; o >>= 1) {
            l += __shfl_xor_sync(0xffffffffu, l, o);
            r += __shfl_xor_sync(0xffffffffu, r, o);
        }
        if (lane == 0) {
            g_el[gw * NHEAD + h] = l;
            g_er[gw * NHEAD + h] = r;
        }
    }
}

// ---------------- fused segment-softmax + aggregation ----------------
__device__ __forceinline__ float4 edge_score(const float* __restrict__ el, int s,
                                             const float4& er) {
    float4 l = *reinterpret_cast<const float4*>(&el[s * 4]);
    float4 v;
    float x;
    x = l.x + er.x; v.x = x > 0.f ? x : 0.2f * x;
    x = l.y + er.y; v.y = x > 0.f ? x : 0.2f * x;
    x = l.z + er.z; v.z = x > 0.f ? x : 0.2f * x;
    x = l.w + er.w; v.w = x > 0.f ? x : 0.2f * x;
    return v;
}

__device__ __forceinline__ void softmax_stats(const float* __restrict__ el, int j0, int j1,
                                              int lane, const float4& er, float* m, float* inv) {
    float s[NHEAD];
#pragma unroll
    for (int h = 0; h < NHEAD; h++) { m[h] = -FLT_MAX; s[h] = 0.f; }
    for (int j = j0 + lane; j < j1; j += 32) {
        float4 e4 = edge_score(el, g_ss[j], er);
        float ev[4] = {e4.x, e4.y, e4.z, e4.w};
#pragma unroll
        for (int h = 0; h < NHEAD; h++) {
            float nm = fmaxf(m[h], ev[h]);
            s[h] = s[h] * __expf(m[h] - nm) + __expf(ev[h] - nm);
            m[h] = nm;
        }
    }
#pragma unroll
    for (int h = 0; h < NHEAD; h++) {
#pragma unroll
        for (int o = 16; o > 0; o >>= 1) {
            float om = __shfl_xor_sync(0xffffffffu, m[h], o);
            float os = __shfl_xor_sync(0xffffffffu, s[h], o);
            float nm = fmaxf(m[h], om);
            s[h] = s[h] * __expf(m[h] - nm) + os * __expf(om - nm);
            m[h] = nm;
        }
    }
#pragma unroll
    for (int h = 0; h < NHEAD; h++) inv[h] = 1.f / fmaxf(s[h], 1e-9f);
}

// hidden layers; SC2: also emit layer-2 scores from the freshly computed h1 row
template <bool SC2>
__global__ void k_softagg_mid(const float* __restrict__ z, const float* __restrict__ bias,
                              float* __restrict__ hout) {
    int n = (blockIdx.x * blockDim.x + threadIdx.x) >> 5;
    int lane = threadIdx.x & 31;
    if (n >= NN) return;
    int j0 = g_off[n], j1 = g_off[n + 1];
    float4 er = *reinterpret_cast<const float4*>(&g_er[n * 4]);
    float m[NHEAD], inv[NHEAD];
    softmax_stats(g_el, j0, j1, lane, er, m, inv);

    float acc[NHEAD][2];
#pragma unroll
    for (int h = 0; h < NHEAD; h++) { acc[h][0] = 0.f; acc[h][1] = 0.f; }
    for (int j = j0; j < j1; j++) {
        int sidx = g_ss[j];
        float4 e4 = edge_score(g_el, sidx, er);
        float a[4];
        a[0] = __expf(e4.x - m[0]) * inv[0];
        a[1] = __expf(e4.y - m[1]) * inv[1];
        a[2] = __expf(e4.z - m[2]) * inv[2];
        a[3] = __expf(e4.w - m[3]) * inv[3];
        const float* zr = z + (size_t)sidx * 256;
#pragma unroll
        for (int h = 0; h < NHEAD; h++) {
            acc[h][0] += a[h] * zr[h * 64 + lane];
            acc[h][1] += a[h] * zr[h * 64 + lane + 32];
        }
    }
    float sl2[NHEAD], sr2[NHEAD];
    if (SC2) {
#pragma unroll
        for (int h = 0; h < NHEAD; h++) { sl2[h] = 0.f; sr2[h] = 0.f; }
    }
#pragma unroll
    for (int h = 0; h < NHEAD; h++) {
        float v0 = acc[h][0] + bias[h * 64 + lane];
        float v1 = acc[h][1] + bias[h * 64 + lane + 32];
        v0 = v0 > 0.f ? v0 : (__expf(v0) - 1.f);
        v1 = v1 > 0.f ? v1 : (__expf(v1) - 1.f);
        size_t i0 = (size_t)n * 256 + h * 64 + lane;
        hout[i0] = v0;
        hout[i0 + 32] = v1;
        __nv_bfloat16 h0 = __float2bfloat16(v0);
        __nv_bfloat16 h1b = __float2bfloat16(v1);
        g_ahi[i0] = h0;
        g_ahi[i0 + 32] = h1b;
        g_alo[i0] = __float2bfloat16(v0 - __bfloat162float(h0));
        g_alo[i0 + 32] = __float2bfloat16(v1 - __bfloat162float(h1b));
        if (SC2) {
            int j0c = h * 64 + lane;
#pragma unroll
            for (int hh = 0; hh < NHEAD; hh++) {
                sl2[hh] += v0 * g_wl2[hh * 256 + j0c] + v1 * g_wl2[hh * 256 + j0c + 32];
                sr2[hh] += v0 * g_wr2[hh * 256 + j0c] + v1 * g_wr2[hh * 256 + j0c + 32];
            }
        }
    }
    if (SC2) {
#pragma unroll
        for (int hh = 0; hh < NHEAD; hh++) {
            float l = sl2[hh], r = sr2[hh];
#pragma unroll
            for (int o = 16; o > 0; o >>= 1) {
                l += __shfl_xor_sync(0xffffffffu, l, o);
                r += __shfl_xor_sync(0xffffffffu, r, o);
            }
            if (lane == 0) {
                g_el2[n * NHEAD + hh] = l;
                g_er2[n * NHEAD + hh] = r;
            }
        }
    }
}

// layer 2: softmax (el2/er2) + aggregate h1 into bf16 split A [N,1024]
__global__ void k_softagg2(const float* __restrict__ h1) {
    int n = (blockIdx.x * blockDim.x + threadIdx.x) >> 5;
    int lane = threadIdx.x & 31;
    if (n >= NN) return;
    int j0 = g_off[n], j1 = g_off[n + 1];
    float4 er = *reinterpret_cast<const float4*>(&g_er2[n * 4]);
    float m[NHEAD], inv[NHEAD];
    softmax_stats(g_el2, j0, j1, lane, er, m, inv);

    float acc[NHEAD][8];
#pragma unroll
    for (int h = 0; h < NHEAD; h++)
#pragma unroll
        for (int p = 0; p < 8; p++) acc[h][p] = 0.f;
    for (int j = j0; j < j1; j++) {
        int sidx = g_ss[j];
        float4 e4 = edge_score(g_el2, sidx, er);
        float a[4];
        a[0] = __expf(e4.x - m[0]) * inv[0];
        a[1] = __expf(e4.y - m[1]) * inv[1];
        a[2] = __expf(e4.z - m[2]) * inv[2];
        a[3] = __expf(e4.w - m[3]) * inv[3];
        const float* hr = h1 + (size_t)sidx * 256;
#pragma unroll
        for (int p = 0; p < 8; p++) {
            float v = hr[lane + 32 * p];
            acc[0][p] += a[0] * v;
            acc[1][p] += a[1] * v;
            acc[2][p] += a[2] * v;
            acc[3][p] += a[3] * v;
        }
    }
    size_t base = (size_t)n * 1024;
#pragma unroll
    for (int h = 0; h < NHEAD; h++)
#pragma unroll
        for (int p = 0; p < 8; p++) {
            float v = acc[h][p];
            size_t idx = base + h * 256 + lane + 32 * p;
            __nv_bfloat16 hi = __float2bfloat16(v);
            g_ahi[idx] = hi;
            g_alo[idx] = __float2bfloat16(v - __bfloat162float(hi));
        }
}

// ---------------- launch ----------------
extern "C" void kernel_launch(void* const* d_in, const int* in_sizes, int n_in,
                              void* d_out, int out_size) {
    const float* feat = (const float*)d_in[0];
    const float* W0 = (const float*)d_in[1];
    const float* al0 = (const float*)d_in[2];
    const float* ar0 = (const float*)d_in[3];
    const float* b0 = (const float*)d_in[4];
    const float* W1 = (const float*)d_in[5];
    const float* al1 = (const float*)d_in[6];
    const float* ar1 = (const float*)d_in[7];
    const float* b1 = (const float*)d_in[8];
    const float* W2 = (const float*)d_in[9];
    const float* al2 = (const float*)d_in[10];
    const float* ar2 = (const float*)d_in[11];
    const float* b2 = (const float*)d_in[12];
    const int* src = (const int*)d_in[13];
    const int* dst = (const int*)d_in[14];
    float* out = (float*)d_out;

    float *p_z, *p_h, *p_bias2;
    __nv_bfloat16 *p_ahi, *p_alo, *p_b0hi, *p_b0lo, *p_b1hi, *p_b1lo, *p_b2hi, *p_b2lo;
    cudaGetSymbolAddress((void**)&p_z, g_z);
    cudaGetSymbolAddress((void**)&p_h, g_h);
    cudaGetSymbolAddress((void**)&p_bias2, g_bias2);
    cudaGetSymbolAddress((void**)&p_ahi, g_ahi);
    cudaGetSymbolAddress((void**)&p_alo, g_alo);
    cudaGetSymbolAddress((void**)&p_b0hi, g_b0hi);
    cudaGetSymbolAddress((void**)&p_b0lo, g_b0lo);
    cudaGetSymbolAddress((void**)&p_b1hi, g_b1hi);
    cudaGetSymbolAddress((void**)&p_b1lo, g_b1lo);
    cudaGetSymbolAddress((void**)&p_b2hi, g_b2hi);
    cudaGetSymbolAddress((void**)&p_b2lo, g_b2lo);

    const int TB = 256;
    int eb = (NE + TB - 1) / TB;
    int nwb = (NN * 32 + TB - 1) / TB;   // one warp per node
    int scb = (NN + 1023) / 1024;
    dim3 ggrid(2, (NN + 127) / 128);

    // front: all weight prep + deg zero, then CSR chain + feat split
    k_prep<<<(PREP_TOT + TB - 1) / TB, TB>>>(W0, W1, W2, al2, ar2, b2);
    k_splitA<<<(NN * 32 + TB - 1) / TB, TB>>>(feat, p_ahi, p_alo, NN * 32);
    k_count<<<eb, TB>>>(dst);
    k_scan1<<<scb, 1024>>>();
    k_scan2<<<scb, 1024>>>();
    k_fill<<<eb, TB>>>(src, dst);

    // ---- layer 0: 128 -> 4x64, ELU
    k_gemm_mma<<<ggrid, 256>>>(p_ahi, p_alo, p_b0hi, p_b0lo, p_z, NN, 256, 128, 1.f, nullptr);
    k_scores<<<nwb, TB>>>(p_z, al0, ar0);
    k_softagg_mid<false><<<nwb, TB>>>(p_z, b0, p_h);

    // ---- layer 1: 256 -> 4x64, ELU (+ fused layer-2 scores)
    k_gemm_mma<<<ggrid, 256>>>(p_ahi, p_alo, p_b1hi, p_b1lo, p_z, NN, 256, 256, 1.f, nullptr);
    k_scores<<<nwb, TB>>>(p_z, al1, ar1);
    k_softagg_mid<true><<<nwb, TB>>>(p_z, b1, p_h);

    // ---- layer 2: softmax+aggregate h1, single GEMM K=1024
    k_softagg2<<<nwb, TB>>>(p_h);
    k_gemm_mma<<<ggrid, 256>>>(p_ahi, p_alo, p_b2hi, p_b2lo, out, NN, 256, 1024, 0.25f, p_bias2);
}

// round 15
// speedup vs baseline: 1.1391x; 1.0531x over previous
#include <cuda_runtime.h>
#include <cuda_bf16.h>
#include <math.h>
#include <float.h>
#include <stdint.h>

#define NN 50000
#define NE 800000
#define NHEAD 4

// ---------------- scratch (device globals; no allocation allowed) ----------------
__device__ float g_z[(size_t)NN * 256];    // GEMM0/1 output (projected feats, fp32)
__device__ float g_h[(size_t)NN * 256];    // hidden activations (fp32, for scores/agg)
__device__ __nv_bfloat16 g_ahi[(size_t)NN * 1024];  // GEMM A operand, bf16 high part
__device__ __nv_bfloat16 g_alo[(size_t)NN * 1024];  // GEMM A operand, bf16 low part
__device__ __nv_bfloat16 g_b0hi[256 * 128], g_b0lo[256 * 128];   // W0^T split
__device__ __nv_bfloat16 g_b1hi[256 * 256], g_b1lo[256 * 256];   // W1^T split
__device__ __nv_bfloat16 g_b2hi[256 * 1024], g_b2lo[256 * 1024]; // W2 permuted split
__device__ float g_el[NN * NHEAD];
__device__ float g_er[NN * NHEAD];
__device__ float g_el2[NN * NHEAD];
__device__ float g_er2[NN * NHEAD];
__device__ int   g_ss[NE];
__device__ int   g_deg[NN];
__device__ int   g_cur[NN];
__device__ int   g_off[NN + 1];
__device__ int   g_bsum[64];
__device__ float g_wl2[NHEAD * 256];
__device__ float g_wr2[NHEAD * 256];
__device__ float g_bias2[256];

// ================= warp-MMA helpers =================
__device__ __forceinline__ uint32_t smem_u32(const void* p) {
    uint32_t a;
    asm("{ .reg .u64 t; cvta.to.shared.u64 t, %1; cvt.u32.u64 %0, t; }" : "=r"(a) : "l"(p));
    return a;
}
#define LDM4(r0, r1, r2, r3, addr) \
    asm volatile("ldmatrix.sync.aligned.m8n8.x4.shared.b16 {%0,%1,%2,%3}, [%4];" \
                 : "=r"(r0), "=r"(r1), "=r"(r2), "=r"(r3) : "r"(addr))
#define MMA16816(d, a, b) \
    asm volatile("mma.sync.aligned.m16n8k16.row.col.f32.bf16.bf16.f32 " \
                 "{%0,%1,%2,%3}, {%4,%5,%6,%7}, {%8,%9}, {%0,%1,%2,%3};" \
                 : "+f"((d)[0]), "+f"((d)[1]), "+f"((d)[2]), "+f"((d)[3]) \
                 : "r"((a)[0]), "r"((a)[1]), "r"((a)[2]), "r"((a)[3]), \
                   "r"((b)[0]), "r"((b)[1]))

// ================= split-bf16 tensor-core GEMM (byte-identical to R7/R9/R14) =================
#define GBM 128
#define GBN 128
#define GBK 32
#define GPAD 40

__global__ void __launch_bounds__(256)
k_gemm_mma(const __nv_bfloat16* __restrict__ Ahi, const __nv_bfloat16* __restrict__ Alo,
           const __nv_bfloat16* __restrict__ Bhi, const __nv_bfloat16* __restrict__ Blo,
           float* __restrict__ C, int M, int N, int K,
           float scale, const float* __restrict__ bias) {
    __shared__ __nv_bfloat16 sAhi[GBM * GPAD];
    __shared__ __nv_bfloat16 sAlo[GBM * GPAD];
    __shared__ __nv_bfloat16 sBhi[GBN * GPAD];
    __shared__ __nv_bfloat16 sBlo[GBN * GPAD];

    int tid = threadIdx.x;
    int lane = tid & 31;
    int wid = tid >> 5;
    int wm = wid >> 2;
    int wn = wid & 3;
    int bm = blockIdx.y * GBM;
    int bn = blockIdx.x * GBN;

    uint32_t bAhi = smem_u32(sAhi), bAlo = smem_u32(sAlo);
    uint32_t bBhi = smem_u32(sBhi), bBlo = smem_u32(sBlo);

    const __nv_bfloat16* gptr[8];
    __nv_bfloat16* sptr[8];
    bool valid[8];
#pragma unroll
    for (int t = 0; t < 8; t++) {
        int idx = tid + t * 256;
        int tile = idx >> 9;
        int u = idx & 511;
        int row = u >> 2;
        int ch = u & 3;
        __nv_bfloat16* sbase = (tile == 0) ? sAhi : (tile == 1) ? sAlo : (tile == 2) ? sBhi : sBlo;
        sptr[t] = sbase + row * GPAD + ch * 8;
        if (tile < 2) {
            int gm = bm + row;
            valid[t] = (gm < M);
            const __nv_bfloat16* gb = (tile == 0) ? Ahi : Alo;
            gptr[t] = gb + (size_t)(valid[t] ? gm : 0) * K + ch * 8;
        } else {
            int gn = bn + row;
            valid[t] = true;
            const __nv_bfloat16* gb = (tile == 2) ? Bhi : Blo;
            gptr[t] = gb + (size_t)gn * K + ch * 8;
        }
    }

    float acc[4][4][4];
#pragma unroll
    for (int i = 0; i < 4; i++)
#pragma unroll
        for (int j = 0; j < 4; j++)
#pragma unroll
            for (int r = 0; r < 4; r++) acc[i][j][r] = 0.f;

    int lrow = lane & 15;
    int lcol = (lane >> 4) * 8;

    int nst = K / GBK;
    uint4 pre[8];
#pragma unroll
    for (int t = 0; t < 8; t++)
        pre[t] = valid[t] ? *reinterpret_cast<const uint4*>(gptr[t]) : make_uint4(0, 0, 0, 0);

    for (int s = 0; s < nst; s++) {
#pragma unroll
        for (int t = 0; t < 8; t++) *reinterpret_cast<uint4*>(sptr[t]) = pre[t];
        __syncthreads();

        if (s + 1 < nst) {
            int k0 = (s + 1) * GBK;
#pragma unroll
            for (int t = 0; t < 8; t++)
                pre[t] = valid[t] ? *reinterpret_cast<const uint4*>(gptr[t] + k0)
                                  : make_uint4(0, 0, 0, 0);
        }

#pragma unroll
        for (int kk = 0; kk < 2; kk++) {
            int kb = kk * 16;
            uint32_t ahi[4][4], alo[4][4];
#pragma unroll
            for (int i = 0; i < 4; i++) {
                uint32_t off = (uint32_t)((wm * 64 + i * 16 + lrow) * GPAD + kb + lcol) * 2;
                LDM4(ahi[i][0], ahi[i][1], ahi[i][2], ahi[i][3], bAhi + off);
                LDM4(alo[i][0], alo[i][1], alo[i][2], alo[i][3], bAlo + off);
            }
            uint32_t bhi[4][2], blo[4][2];
#pragma unroll
            for (int j = 0; j < 2; j++) {
                uint32_t off = (uint32_t)((wn * 32 + j * 16 + lrow) * GPAD + kb + lcol) * 2;
                uint32_t r0, r1, r2, r3;
                LDM4(r0, r1, r2, r3, bBhi + off);
                bhi[2 * j][0] = r0; bhi[2 * j][1] = r2;
                bhi[2 * j + 1][0] = r1; bhi[2 * j + 1][1] = r3;
                LDM4(r0, r1, r2, r3, bBlo + off);
                blo[2 * j][0] = r0; blo[2 * j][1] = r2;
                blo[2 * j + 1][0] = r1; blo[2 * j + 1][1] = r3;
            }
#pragma unroll
            for (int i = 0; i < 4; i++)
#pragma unroll
                for (int n = 0; n < 4; n++) {
                    MMA16816(acc[i][n], ahi[i], bhi[n]);
                    MMA16816(acc[i][n], ahi[i], blo[n]);
                    MMA16816(acc[i][n], alo[i], bhi[n]);
                }
        }
        __syncthreads();
    }

    int g = lane >> 2, tg = lane & 3;
#pragma unroll
    for (int mi = 0; mi < 4; mi++) {
        int r0 = bm + wm * 64 + mi * 16 + g;
        int r1 = r0 + 8;
#pragma unroll
        for (int ni = 0; ni < 4; ni++) {
            int c = bn + wn * 32 + ni * 8 + tg * 2;
            float b0 = 0.f, b1 = 0.f;
            if (bias) { b0 = bias[c]; b1 = bias[c + 1]; }
            if (r0 < M) {
                float2 v = make_float2(scale * acc[mi][ni][0] + b0,
                                       scale * acc[mi][ni][1] + b1);
                *reinterpret_cast<float2*>(&C[(size_t)r0 * N + c]) = v;
            }
            if (r1 < M) {
                float2 v = make_float2(scale * acc[mi][ni][2] + b0,
                                       scale * acc[mi][ni][3] + b1);
                *reinterpret_cast<float2*>(&C[(size_t)r1 * N + c]) = v;
            }
        }
    }
}

// ================= mega prep: feat split + zero deg + wl2/wr2/bias2 + weight splits =================
__device__ __forceinline__ void split1(float f, __nv_bfloat16* hi, __nv_bfloat16* lo, int i) {
    __nv_bfloat16 h = __float2bfloat16(f);
    hi[i] = h;
    lo[i] = __float2bfloat16(f - __bfloat162float(h));
}

#define PREP_FEAT (NN * 32)                 // feat split, float4 granularity
#define PREP_DEG  (PREP_FEAT + NN)
#define PREP_WLR  (PREP_DEG + 2048)
#define PREP_B2   (PREP_WLR + 256)
#define PREP_W0   (PREP_B2 + 256 * 128)
#define PREP_W1   (PREP_W0 + 256 * 256)
#define PREP_TOT  (PREP_W1 + 256 * 1024)

__global__ void k_prep(const float* __restrict__ feat,
                       const float* __restrict__ W0, const float* __restrict__ W1,
                       const float* __restrict__ W2, const float* __restrict__ al2,
                       const float* __restrict__ ar2, const float* __restrict__ b2) {
    int t = blockIdx.x * blockDim.x + threadIdx.x;
    if (t < PREP_FEAT) {
        float4 f = reinterpret_cast<const float4*>(feat)[t];
        __nv_bfloat16 h0 = __float2bfloat16(f.x), h1 = __float2bfloat16(f.y);
        __nv_bfloat16 h2 = __float2bfloat16(f.z), h3 = __float2bfloat16(f.w);
        __nv_bfloat162* hp = reinterpret_cast<__nv_bfloat162*>(g_ahi + 4 * (size_t)t);
        hp[0] = __nv_bfloat162(h0, h1);
        hp[1] = __nv_bfloat162(h2, h3);
        __nv_bfloat162* lp = reinterpret_cast<__nv_bfloat162*>(g_alo + 4 * (size_t)t);
        lp[0] = __nv_bfloat162(__float2bfloat16(f.x - __bfloat162float(h0)),
                               __float2bfloat16(f.y - __bfloat162float(h1)));
        lp[1] = __nv_bfloat162(__float2bfloat16(f.z - __bfloat162float(h2)),
                               __float2bfloat16(f.w - __bfloat162float(h3)));
    } else if (t < PREP_DEG) {
        g_deg[t - PREP_FEAT] = 0;
    } else if (t < PREP_WLR) {
        int u = t - PREP_DEG;
        int which = u >> 10;
        int hk = u & 1023;
        int h = hk >> 8, k = hk & 255;
        const float* a = (which == 0 ? al2 : ar2) + h * 256;
        const float* wrow = W2 + (size_t)k * 1024 + h * 256;
        float s = 0.f;
#pragma unroll 8
        for (int c = 0; c < 256; c++) s += wrow[c] * a[c];
        if (which == 0) g_wl2[hk] = s;
        else            g_wr2[hk] = s;
    } else if (t < PREP_B2) {
        int c = t - PREP_WLR;
        g_bias2[c] = 0.25f * (b2[c] + b2[256 + c] + b2[512 + c] + b2[768 + c]);
    } else if (t < PREP_W0) {
        int idx = t - PREP_B2;           // W0^T: [256,128]
        int n = idx >> 7, k = idx & 127;
        split1(W0[(size_t)k * 256 + n], g_b0hi, g_b0lo, idx);
    } else if (t < PREP_W1) {
        int idx = t - PREP_W0;           // W1^T: [256,256]
        int n = idx >> 8, k = idx & 255;
        split1(W1[(size_t)k * 256 + n], g_b1hi, g_b1lo, idx);
    } else if (t < PREP_TOT) {
        int idx = t - PREP_W1;           // W2 permuted: out[c][h*256+kk] = W2[kk*1024+h*256+c]
        int c = idx >> 10;
        int r = idx & 1023;
        int h = r >> 8, kk = r & 255;
        split1(W2[(size_t)kk * 1024 + h * 256 + c], g_b2hi, g_b2lo, idx);
    }
}

// ---------------- CSR build (by destination) ----------------
__global__ void k_count(const int* __restrict__ dst) {
    int i = blockIdx.x * blockDim.x + threadIdx.x;
    if (i < NE) atomicAdd(&g_deg[dst[i]], 1);
}

__global__ void k_scan1() {
    __shared__ int warpsum[32];
    int b = blockIdx.x, tid = threadIdx.x;
    int lane = tid & 31, wrp = tid >> 5;
    int i = b * 1024 + tid;
    int v = (i < NN) ? g_deg[i] : 0;
    int x = v;
#pragma unroll
    for (int o = 1; o < 32; o <<= 1) {
        int t = __shfl_up_sync(0xffffffffu, x, o);
        if (lane >= o) x += t;
    }
    if (lane == 31) warpsum[wrp] = x;
    __syncthreads();
    if (wrp == 0) {
        int w = warpsum[lane];
#pragma unroll
        for (int o = 1; o < 32; o <<= 1) {
            int t = __shfl_up_sync(0xffffffffu, w, o);
            if (lane >= o) w += t;
        }
        warpsum[lane] = w;
    }
    __syncthreads();
    int excl = (wrp ? warpsum[wrp - 1] : 0) + x - v;
    if (i < NN) g_off[i] = excl;
    if (tid == 0) g_bsum[b] = warpsum[31];
}

__global__ void k_scan2() {
    __shared__ int boff_s;
    int b = blockIdx.x, tid = threadIdx.x;
    if (tid == 0) boff_s = 0;
    __syncthreads();
    if (tid < b) atomicAdd(&boff_s, g_bsum[tid]);
    __syncthreads();
    int boff = boff_s;
    int i = b * 1024 + tid;
    if (i < NN) {
        int o = g_off[i] + boff;
        g_off[i] = o;
        g_cur[i] = o;
    }
    if (b == gridDim.x - 1 && tid == 0) g_off[NN] = boff + g_bsum[b];
}

__global__ void k_fill(const int* __restrict__ src, const int* __restrict__ dst) {
    int i = blockIdx.x * blockDim.x + threadIdx.x;
    if (i < NE) {
        int d = dst[i];
        int p = atomicAdd(&g_cur[d], 1);
        g_ss[p] = src[i];
    }
}

// ---------------- per-node attention scores (layers 0/1), vectorized ----------------
__global__ void k_scores(const float* __restrict__ z, const float* __restrict__ al,
                         const float* __restrict__ ar) {
    int gw = (blockIdx.x * blockDim.x + threadIdx.x) >> 5;
    int lane = threadIdx.x & 31;
    if (gw >= NN) return;
    const float4* row4 = reinterpret_cast<const float4*>(z + (size_t)gw * 256);
    const float4* al4 = reinterpret_cast<const float4*>(al);
    const float4* ar4 = reinterpret_cast<const float4*>(ar);
    float4 f0 = row4[lane], f1 = row4[32 + lane];
    float4 a0 = al4[lane], a1 = al4[32 + lane];
    float4 r0 = ar4[lane], r1 = ar4[32 + lane];
    int h0 = lane >> 4;        // c=0 chunk: cols lane*4  -> head 0/1
    int h1i = 2 + (lane >> 4); // c=1 chunk: cols 128+lane*4 -> head 2/3
    float accl[NHEAD] = {0.f, 0.f, 0.f, 0.f};
    float accr[NHEAD] = {0.f, 0.f, 0.f, 0.f};
    accl[h0] = f0.x * a0.x + f0.y * a0.y + f0.z * a0.z + f0.w * a0.w;
    accr[h0] = f0.x * r0.x + f0.y * r0.y + f0.z * r0.z + f0.w * r0.w;
    accl[h1i] = f1.x * a1.x + f1.y * a1.y + f1.z * a1.z + f1.w * a1.w;
    accr[h1i] = f1.x * r1.x + f1.y * r1.y + f1.z * r1.z + f1.w * r1.w;
#pragma unroll
    for (int h = 0; h < NHEAD; h++) {
        float l = accl[h], r = accr[h];
#pragma unroll
        for (int o = 16; o > 0; o >>= 1) {
            l += __shfl_xor_sync(0xffffffffu, l, o);
            r += __shfl_xor_sync(0xffffffffu, r, o);
        }
        if (lane == 0) {
            g_el[gw * NHEAD + h] = l;
            g_er[gw * NHEAD + h] = r;
        }
    }
}

// ---------------- fused segment-softmax + aggregation ----------------
__device__ __forceinline__ float4 edge_score(const float* __restrict__ el, int s,
                                             const float4& er) {
    float4 l = *reinterpret_cast<const float4*>(&el[s * 4]);
    float4 v;
    float x;
    x = l.x + er.x; v.x = x > 0.f ? x : 0.2f * x;
    x = l.y + er.y; v.y = x > 0.f ? x : 0.2f * x;
    x = l.z + er.z; v.z = x > 0.f ? x : 0.2f * x;
    x = l.w + er.w; v.w = x > 0.f ? x : 0.2f * x;
    return v;
}

__device__ __forceinline__ void softmax_stats(const float* __restrict__ el, int j0, int j1,
                                              int lane, const float4& er, float* m, float* inv) {
    float s[NHEAD];
#pragma unroll
    for (int h = 0; h < NHEAD; h++) { m[h] = -FLT_MAX; s[h] = 0.f; }
    for (int j = j0 + lane; j < j1; j += 32) {
        float4 e4 = edge_score(el, g_ss[j], er);
        float ev[4] = {e4.x, e4.y, e4.z, e4.w};
#pragma unroll
        for (int h = 0; h < NHEAD; h++) {
            float nm = fmaxf(m[h], ev[h]);
            s[h] = s[h] * __expf(m[h] - nm) + __expf(ev[h] - nm);
            m[h] = nm;
        }
    }
#pragma unroll
    for (int h = 0; h < NHEAD; h++) {
#pragma unroll
        for (int o = 16; o > 0; o >>= 1) {
            float om = __shfl_xor_sync(0xffffffffu, m[h], o);
            float os = __shfl_xor_sync(0xffffffffu, s[h], o);
            float nm = fmaxf(m[h], om);
            s[h] = s[h] * __expf(m[h] - nm) + os * __expf(om - nm);
            m[h] = nm;
        }
    }
#pragma unroll
    for (int h = 0; h < NHEAD; h++) inv[h] = 1.f / fmaxf(s[h], 1e-9f);
}

__device__ __forceinline__ uint2 pack_hi4(const float* v) {
    __nv_bfloat162 p0(__float2bfloat16(v[0]), __float2bfloat16(v[1]));
    __nv_bfloat162 p1(__float2bfloat16(v[2]), __float2bfloat16(v[3]));
    uint2 r;
    r.x = *reinterpret_cast<uint32_t*>(&p0);
    r.y = *reinterpret_cast<uint32_t*>(&p1);
    return r;
}
__device__ __forceinline__ uint2 pack_lo4(const float* v) {
    float l0 = v[0] - __bfloat162float(__float2bfloat16(v[0]));
    float l1 = v[1] - __bfloat162float(__float2bfloat16(v[1]));
    float l2 = v[2] - __bfloat162float(__float2bfloat16(v[2]));
    float l3 = v[3] - __bfloat162float(__float2bfloat16(v[3]));
    __nv_bfloat162 p0(__float2bfloat16(l0), __float2bfloat16(l1));
    __nv_bfloat162 p1(__float2bfloat16(l2), __float2bfloat16(l3));
    uint2 r;
    r.x = *reinterpret_cast<uint32_t*>(&p0);
    r.y = *reinterpret_cast<uint32_t*>(&p1);
    return r;
}

// hidden layers; lane covers cols {c*128 + lane*4 .. +3}, c=0,1; head = c*2 + (lane>>4)
template <bool SC2>
__global__ void k_softagg_mid(const float* __restrict__ z, const float* __restrict__ bias,
                              float* __restrict__ hout) {
    int n = (blockIdx.x * blockDim.x + threadIdx.x) >> 5;
    int lane = threadIdx.x & 31;
    if (n >= NN) return;
    int j0 = g_off[n], j1 = g_off[n + 1];
    float4 er = *reinterpret_cast<const float4*>(&g_er[n * 4]);
    float m[NHEAD], inv[NHEAD];
    softmax_stats(g_el, j0, j1, lane, er, m, inv);

    int hA = lane >> 4;        // head for c=0
    int hB = 2 + (lane >> 4);  // head for c=1
    float acc0[4] = {0.f, 0.f, 0.f, 0.f};
    float acc1[4] = {0.f, 0.f, 0.f, 0.f};
    for (int j = j0; j < j1; j++) {
        int sidx = g_ss[j];
        float4 e4 = edge_score(g_el, sidx, er);
        float a[4];
        a[0] = __expf(e4.x - m[0]) * inv[0];
        a[1] = __expf(e4.y - m[1]) * inv[1];
        a[2] = __expf(e4.z - m[2]) * inv[2];
        a[3] = __expf(e4.w - m[3]) * inv[3];
        const float4* zr = reinterpret_cast<const float4*>(z + (size_t)sidx * 256);
        float4 f0 = zr[lane];
        float4 f1 = zr[32 + lane];
        float aA = a[hA], aB = a[hB];
        acc0[0] += aA * f0.x; acc0[1] += aA * f0.y; acc0[2] += aA * f0.z; acc0[3] += aA * f0.w;
        acc1[0] += aB * f1.x; acc1[1] += aB * f1.y; acc1[2] += aB * f1.z; acc1[3] += aB * f1.w;
    }

    float sl2[NHEAD], sr2[NHEAD];
    if (SC2) {
#pragma unroll
        for (int h = 0; h < NHEAD; h++) { sl2[h] = 0.f; sr2[h] = 0.f; }
    }
    const float4* b4 = reinterpret_cast<const float4*>(bias);
    size_t rowb = (size_t)n * 256;
#pragma unroll
    for (int c = 0; c < 2; c++) {
        float* acc = c ? acc1 : acc0;
        float4 bb = b4[c * 32 + lane];
        float v[4];
        v[0] = acc[0] + bb.x; v[1] = acc[1] + bb.y;
        v[2] = acc[2] + bb.z; v[3] = acc[3] + bb.w;
#pragma unroll
        for (int i = 0; i < 4; i++) v[i] = v[i] > 0.f ? v[i] : (__expf(v[i]) - 1.f);
        int col0 = c * 128 + lane * 4;
        *reinterpret_cast<float4*>(hout + rowb + col0) = make_float4(v[0], v[1], v[2], v[3]);
        *reinterpret_cast<uint2*>(g_ahi + rowb + col0) = pack_hi4(v);
        *reinterpret_cast<uint2*>(g_alo + rowb + col0) = pack_lo4(v);
        if (SC2) {
#pragma unroll
            for (int hh = 0; hh < NHEAD; hh++) {
                const float* wl = g_wl2 + hh * 256 + col0;
                const float* wr = g_wr2 + hh * 256 + col0;
#pragma unroll
                for (int i = 0; i < 4; i++) {
                    sl2[hh] += v[i] * wl[i];
                    sr2[hh] += v[i] * wr[i];
                }
            }
        }
    }
    if (SC2) {
#pragma unroll
        for (int hh = 0; hh < NHEAD; hh++) {
            float l = sl2[hh], r = sr2[hh];
#pragma unroll
            for (int o = 16; o > 0; o >>= 1) {
                l += __shfl_xor_sync(0xffffffffu, l, o);
                r += __shfl_xor_sync(0xffffffffu, r, o);
            }
            if (lane == 0) {
                g_el2[n * NHEAD + hh] = l;
                g_er2[n * NHEAD + hh] = r;
            }
        }
    }
}

// layer 2: softmax (el2/er2) + aggregate h1 into bf16 split A [N,1024]
// lane reads h1 row as 2 float4s (cols c*128+lane*4); output has all 4 head copies.
__global__ void k_softagg2(const float* __restrict__ h1) {
    int n = (blockIdx.x * blockDim.x + threadIdx.x) >> 5;
    int lane = threadIdx.x & 31;
    if (n >= NN) return;
    int j0 = g_off[n], j1 = g_off[n + 1];
    float4 er = *reinterpret_cast<const float4*>(&g_er2[n * 4]);
    float m[NHEAD], inv[NHEAD];
    softmax_stats(g_el2, j0, j1, lane, er, m, inv);

    float acc[NHEAD][2][4];
#pragma unroll
    for (int h = 0; h < NHEAD; h++)
#pragma unroll
        for (int c = 0; c < 2; c++)
#pragma unroll
            for (int i = 0; i < 4; i++) acc[h][c][i] = 0.f;
    for (int j = j0; j < j1; j++) {
        int sidx = g_ss[j];
        float4 e4 = edge_score(g_el2, sidx, er);
        float a[4];
        a[0] = __expf(e4.x - m[0]) * inv[0];
        a[1] = __expf(e4.y - m[1]) * inv[1];
        a[2] = __expf(e4.z - m[2]) * inv[2];
        a[3] = __expf(e4.w - m[3]) * inv[3];
        const float4* hr = reinterpret_cast<const float4*>(h1 + (size_t)sidx * 256);
        float4 f0 = hr[lane];
        float4 f1 = hr[32 + lane];
#pragma unroll
        for (int h = 0; h < NHEAD; h++) {
            acc[h][0][0] += a[h] * f0.x; acc[h][0][1] += a[h] * f0.y;
            acc[h][0][2] += a[h] * f0.z; acc[h][0][3] += a[h] * f0.w;
            acc[h][1][0] += a[h] * f1.x; acc[h][1][1] += a[h] * f1.y;
            acc[h][1][2] += a[h] * f1.z; acc[h][1][3] += a[h] * f1.w;
        }
    }
    size_t base = (size_t)n * 1024;
#pragma unroll
    for (int h = 0; h < NHEAD; h++)
#pragma unroll
        for (int c = 0; c < 2; c++) {
            int col0 = h * 256 + c * 128 + lane * 4;
            *reinterpret_cast<uint2*>(g_ahi + base + col0) = pack_hi4(acc[h][c]);
            *reinterpret_cast<uint2*>(g_alo + base + col0) = pack_lo4(acc[h][c]);
        }
}

// ---------------- launch ----------------
extern "C" void kernel_launch(void* const* d_in, const int* in_sizes, int n_in,
                              void* d_out, int out_size) {
    const float* feat = (const float*)d_in[0];
    const float* W0 = (const float*)d_in[1];
    const float* al0 = (const float*)d_in[2];
    const float* ar0 = (const float*)d_in[3];
    const float* b0 = (const float*)d_in[4];
    const float* W1 = (const float*)d_in[5];
    const float* al1 = (const float*)d_in[6];
    const float* ar1 = (const float*)d_in[7];
    const float* b1 = (const float*)d_in[8];
    const float* W2 = (const float*)d_in[9];
    const float* al2 = (const float*)d_in[10];
    const float* ar2 = (const float*)d_in[11];
    const float* b2 = (const float*)d_in[12];
    const int* src = (const int*)d_in[13];
    const int* dst = (const int*)d_in[14];
    float* out = (float*)d_out;

    float *p_z, *p_h, *p_bias2;
    __nv_bfloat16 *p_ahi, *p_alo, *p_b0hi, *p_b0lo, *p_b1hi, *p_b1lo, *p_b2hi, *p_b2lo;
    cudaGetSymbolAddress((void**)&p_z, g_z);
    cudaGetSymbolAddress((void**)&p_h, g_h);
    cudaGetSymbolAddress((void**)&p_bias2, g_bias2);
    cudaGetSymbolAddress((void**)&p_ahi, g_ahi);
    cudaGetSymbolAddress((void**)&p_alo, g_alo);
    cudaGetSymbolAddress((void**)&p_b0hi, g_b0hi);
    cudaGetSymbolAddress((void**)&p_b0lo, g_b0lo);
    cudaGetSymbolAddress((void**)&p_b1hi, g_b1hi);
    cudaGetSymbolAddress((void**)&p_b1lo, g_b1lo);
    cudaGetSymbolAddress((void**)&p_b2hi, g_b2hi);
    cudaGetSymbolAddress((void**)&p_b2lo, g_b2lo);

    const int TB = 256;
    int eb = (NE + TB - 1) / TB;
    int nwb = (NN * 32 + TB - 1) / TB;   // one warp per node
    int scb = (NN + 1023) / 1024;
    dim3 ggrid(2, (NN + 127) / 128);

    // front: all prep + feat split + CSR chain
    k_prep<<<(PREP_TOT + TB - 1) / TB, TB>>>(feat, W0, W1, W2, al2, ar2, b2);
    k_count<<<eb, TB>>>(dst);
    k_scan1<<<scb, 1024>>>();
    k_scan2<<<scb, 1024>>>();
    k_fill<<<eb, TB>>>(src, dst);

    // ---- layer 0: 128 -> 4x64, ELU
    k_gemm_mma<<<ggrid, 256>>>(p_ahi, p_alo, p_b0hi, p_b0lo, p_z, NN, 256, 128, 1.f, nullptr);
    k_scores<<<nwb, TB>>>(p_z, al0, ar0);
    k_softagg_mid<false><<<nwb, TB>>>(p_z, b0, p_h);

    // ---- layer 1: 256 -> 4x64, ELU (+ fused layer-2 scores)
    k_gemm_mma<<<ggrid, 256>>>(p_ahi, p_alo, p_b1hi, p_b1lo, p_z, NN, 256, 256, 1.f, nullptr);
    k_scores<<<nwb, TB>>>(p_z, al1, ar1);
    k_softagg_mid<true><<<nwb, TB>>>(p_z, b1, p_h);

    // ---- layer 2: softmax+aggregate h1, single GEMM K=1024
    k_softagg2<<<nwb, TB>>>(p_h);
    k_gemm_mma<<<ggrid, 256>>>(p_ahi, p_alo, p_b2hi, p_b2lo, out, NN, 256, 1024, 0.25f, p_bias2);
}

// round 17
// speedup vs baseline: 1.1411x; 1.0017x over previous
#include <cuda_runtime.h>
#include <cuda_bf16.h>
#include <math.h>
#include <float.h>
#include <stdint.h>

#define NN 50000
#define NE 800000
#define NHEAD 4

// ---------------- scratch (device globals; no allocation allowed) ----------------
__device__ float g_z[(size_t)NN * 256];    // GEMM0/1 output (projected feats, fp32)
__device__ float g_h[(size_t)NN * 256];    // hidden activations (fp32, for scores/agg)
__device__ __nv_bfloat16 g_ahi[(size_t)NN * 1024];  // GEMM A operand, bf16 high part
__device__ __nv_bfloat16 g_alo[(size_t)NN * 1024];  // GEMM A operand, bf16 low part
__device__ __nv_bfloat16 g_b0hi[256 * 128], g_b0lo[256 * 128];   // W0^T split
__device__ __nv_bfloat16 g_b1hi[256 * 256], g_b1lo[256 * 256];   // W1^T split
__device__ __nv_bfloat16 g_b2hi[256 * 1024], g_b2lo[256 * 1024]; // W2 permuted split
__device__ float g_el[NN * NHEAD];
__device__ float g_er[NN * NHEAD];
__device__ float g_el2[NN * NHEAD];
__device__ float g_er2[NN * NHEAD];
__device__ int   g_ss[NE];
__device__ int   g_deg[NN];
__device__ int   g_cur[NN];
__device__ int   g_off[NN + 1];
__device__ int   g_bsum[64];
__device__ float g_wl2[NHEAD * 256];
__device__ float g_wr2[NHEAD * 256];
__device__ float g_bias2[256];

// ================= warp-MMA helpers =================
__device__ __forceinline__ uint32_t smem_u32(const void* p) {
    uint32_t a;
    asm("{ .reg .u64 t; cvta.to.shared.u64 t, %1; cvt.u32.u64 %0, t; }" : "=r"(a) : "l"(p));
    return a;
}
#define LDM4(r0, r1, r2, r3, addr) \
    asm volatile("ldmatrix.sync.aligned.m8n8.x4.shared.b16 {%0,%1,%2,%3}, [%4];" \
                 : "=r"(r0), "=r"(r1), "=r"(r2), "=r"(r3) : "r"(addr))
#define MMA16816(d, a, b) \
    asm volatile("mma.sync.aligned.m16n8k16.row.col.f32.bf16.bf16.f32 " \
                 "{%0,%1,%2,%3}, {%4,%5,%6,%7}, {%8,%9}, {%0,%1,%2,%3};" \
                 : "+f"((d)[0]), "+f"((d)[1]), "+f"((d)[2]), "+f"((d)[3]) \
                 : "r"((a)[0]), "r"((a)[1]), "r"((a)[2]), "r"((a)[3]), \
                   "r"((b)[0]), "r"((b)[1]))

// ================= split-bf16 tensor-core GEMM (mainloop byte-identical to R7..R15) =================
// New: optional fused score epilogue — if al!=nullptr, atomically accumulates
// el[n,h]=sum_c z[n,c]*al[c], er likewise. Exactly 2 atomic adds per (n,h) (commutative
// 2-sum => bitwise deterministic). Requires g_el/g_er zeroed before launch.
#define GBM 128
#define GBN 128
#define GBK 32
#define GPAD 40

__global__ void __launch_bounds__(256)
k_gemm_mma(const __nv_bfloat16* __restrict__ Ahi, const __nv_bfloat16* __restrict__ Alo,
           const __nv_bfloat16* __restrict__ Bhi, const __nv_bfloat16* __restrict__ Blo,
           float* __restrict__ C, int M, int N, int K,
           float scale, const float* __restrict__ bias,
           const float* __restrict__ al, const float* __restrict__ ar) {
    __shared__ __nv_bfloat16 sAhi[GBM * GPAD];
    __shared__ __nv_bfloat16 sAlo[GBM * GPAD];
    __shared__ __nv_bfloat16 sBhi[GBN * GPAD];
    __shared__ __nv_bfloat16 sBlo[GBN * GPAD];

    int tid = threadIdx.x;
    int lane = tid & 31;
    int wid = tid >> 5;
    int wm = wid >> 2;
    int wn = wid & 3;
    int bm = blockIdx.y * GBM;
    int bn = blockIdx.x * GBN;

    uint32_t bAhi = smem_u32(sAhi), bAlo = smem_u32(sAlo);
    uint32_t bBhi = smem_u32(sBhi), bBlo = smem_u32(sBlo);

    const __nv_bfloat16* gptr[8];
    __nv_bfloat16* sptr[8];
    bool valid[8];
#pragma unroll
    for (int t = 0; t < 8; t++) {
        int idx = tid + t * 256;
        int tile = idx >> 9;
        int u = idx & 511;
        int row = u >> 2;
        int ch = u & 3;
        __nv_bfloat16* sbase = (tile == 0) ? sAhi : (tile == 1) ? sAlo : (tile == 2) ? sBhi : sBlo;
        sptr[t] = sbase + row * GPAD + ch * 8;
        if (tile < 2) {
            int gm = bm + row;
            valid[t] = (gm < M);
            const __nv_bfloat16* gb = (tile == 0) ? Ahi : Alo;
            gptr[t] = gb + (size_t)(valid[t] ? gm : 0) * K + ch * 8;
        } else {
            int gn = bn + row;
            valid[t] = true;
            const __nv_bfloat16* gb = (tile == 2) ? Bhi : Blo;
            gptr[t] = gb + (size_t)gn * K + ch * 8;
        }
    }

    float acc[4][4][4];
#pragma unroll
    for (int i = 0; i < 4; i++)
#pragma unroll
        for (int j = 0; j < 4; j++)
#pragma unroll
            for (int r = 0; r < 4; r++) acc[i][j][r] = 0.f;

    int lrow = lane & 15;
    int lcol = (lane >> 4) * 8;

    int nst = K / GBK;
    uint4 pre[8];
#pragma unroll
    for (int t = 0; t < 8; t++)
        pre[t] = valid[t] ? *reinterpret_cast<const uint4*>(gptr[t]) : make_uint4(0, 0, 0, 0);

    for (int s = 0; s < nst; s++) {
#pragma unroll
        for (int t = 0; t < 8; t++) *reinterpret_cast<uint4*>(sptr[t]) = pre[t];
        __syncthreads();

        if (s + 1 < nst) {
            int k0 = (s + 1) * GBK;
#pragma unroll
            for (int t = 0; t < 8; t++)
                pre[t] = valid[t] ? *reinterpret_cast<const uint4*>(gptr[t] + k0)
                                  : make_uint4(0, 0, 0, 0);
        }

#pragma unroll
        for (int kk = 0; kk < 2; kk++) {
            int kb = kk * 16;
            uint32_t ahi[4][4], alo[4][4];
#pragma unroll
            for (int i = 0; i < 4; i++) {
                uint32_t off = (uint32_t)((wm * 64 + i * 16 + lrow) * GPAD + kb + lcol) * 2;
                LDM4(ahi[i][0], ahi[i][1], ahi[i][2], ahi[i][3], bAhi + off);
                LDM4(alo[i][0], alo[i][1], alo[i][2], alo[i][3], bAlo + off);
            }
            uint32_t bhi[4][2], blo[4][2];
#pragma unroll
            for (int j = 0; j < 2; j++) {
                uint32_t off = (uint32_t)((wn * 32 + j * 16 + lrow) * GPAD + kb + lcol) * 2;
                uint32_t r0, r1, r2, r3;
                LDM4(r0, r1, r2, r3, bBhi + off);
                bhi[2 * j][0] = r0; bhi[2 * j][1] = r2;
                bhi[2 * j + 1][0] = r1; bhi[2 * j + 1][1] = r3;
                LDM4(r0, r1, r2, r3, bBlo + off);
                blo[2 * j][0] = r0; blo[2 * j][1] = r2;
                blo[2 * j + 1][0] = r1; blo[2 * j + 1][1] = r3;
            }
#pragma unroll
            for (int i = 0; i < 4; i++)
#pragma unroll
                for (int n = 0; n < 4; n++) {
                    MMA16816(acc[i][n], ahi[i], bhi[n]);
                    MMA16816(acc[i][n], ahi[i], blo[n]);
                    MMA16816(acc[i][n], alo[i], bhi[n]);
                }
        }
        __syncthreads();
    }

    int g = lane >> 2, tg = lane & 3;
#pragma unroll
    for (int mi = 0; mi < 4; mi++) {
        int r0 = bm + wm * 64 + mi * 16 + g;
        int r1 = r0 + 8;
#pragma unroll
        for (int ni = 0; ni < 4; ni++) {
            int c = bn + wn * 32 + ni * 8 + tg * 2;
            float b0 = 0.f, b1 = 0.f;
            if (bias) { b0 = bias[c]; b1 = bias[c + 1]; }
            if (r0 < M) {
                float2 v = make_float2(scale * acc[mi][ni][0] + b0,
                                       scale * acc[mi][ni][1] + b1);
                *reinterpret_cast<float2*>(&C[(size_t)r0 * N + c]) = v;
            }
            if (r1 < M) {
                float2 v = make_float2(scale * acc[mi][ni][2] + b0,
                                       scale * acc[mi][ni][3] + b1);
                *reinterpret_cast<float2*>(&C[(size_t)r1 * N + c]) = v;
            }
        }
    }

    // ---- fused score epilogue (el/er) ----
    if (al) {
        int head = (bn >> 6) + (wn >> 1);
#pragma unroll
        for (int mi = 0; mi < 4; mi++) {
            float sl0 = 0.f, sr0 = 0.f, sl1 = 0.f, sr1 = 0.f;
#pragma unroll
            for (int ni = 0; ni < 4; ni++) {
                int c = bn + wn * 32 + ni * 8 + tg * 2;
                float a0 = al[c], a1 = al[c + 1];
                float q0 = ar[c], q1 = ar[c + 1];
                sl0 += acc[mi][ni][0] * a0 + acc[mi][ni][1] * a1;
                sr0 += acc[mi][ni][0] * q0 + acc[mi][ni][1] * q1;
                sl1 += acc[mi][ni][2] * a0 + acc[mi][ni][3] * a1;
                sr1 += acc[mi][ni][2] * q0 + acc[mi][ni][3] * q1;
            }
            // reduce across the 4 tg lanes of the quad (same row group g)
            sl0 += __shfl_xor_sync(0xffffffffu, sl0, 1);
            sl0 += __shfl_xor_sync(0xffffffffu, sl0, 2);
            sr0 += __shfl_xor_sync(0xffffffffu, sr0, 1);
            sr0 += __shfl_xor_sync(0xffffffffu, sr0, 2);
            sl1 += __shfl_xor_sync(0xffffffffu, sl1, 1);
            sl1 += __shfl_xor_sync(0xffffffffu, sl1, 2);
            sr1 += __shfl_xor_sync(0xffffffffu, sr1, 1);
            sr1 += __shfl_xor_sync(0xffffffffu, sr1, 2);
            if (tg == 0) {
                int r0 = bm + wm * 64 + mi * 16 + g;
                int r1 = r0 + 8;
                if (r0 < M) {
                    atomicAdd(&g_el[r0 * NHEAD + head], sl0);
                    atomicAdd(&g_er[r0 * NHEAD + head], sr0);
                }
                if (r1 < M) {
                    atomicAdd(&g_el[r1 * NHEAD + head], sl1);
                    atomicAdd(&g_er[r1 * NHEAD + head], sr1);
                }
            }
        }
    }
}

// ================= mega prep: feat split + zero deg/el/er + wl2/wr2/bias2 + weight splits =================
__device__ __forceinline__ void split1(float f, __nv_bfloat16* hi, __nv_bfloat16* lo, int i) {
    __nv_bfloat16 h = __float2bfloat16(f);
    hi[i] = h;
    lo[i] = __float2bfloat16(f - __bfloat162float(h));
}

#define PREP_FEAT (NN * 32)                 // feat split, float4 granularity
#define PREP_DEG  (PREP_FEAT + NN)
#define PREP_ELZ  (PREP_DEG + NN * NHEAD)   // zero g_el & g_er (paired)
#define PREP_WLR  (PREP_ELZ + 2048)
#define PREP_B2   (PREP_WLR + 256)
#define PREP_W0   (PREP_B2 + 256 * 128)
#define PREP_W1   (PREP_W0 + 256 * 256)
#define PREP_TOT  (PREP_W1 + 256 * 1024)

__global__ void k_prep(const float* __restrict__ feat,
                       const float* __restrict__ W0, const float* __restrict__ W1,
                       const float* __restrict__ W2, const float* __restrict__ al2,
                       const float* __restrict__ ar2, const float* __restrict__ b2) {
    int t = blockIdx.x * blockDim.x + threadIdx.x;
    if (t < PREP_FEAT) {
        float4 f = reinterpret_cast<const float4*>(feat)[t];
        __nv_bfloat16 h0 = __float2bfloat16(f.x), h1 = __float2bfloat16(f.y);
        __nv_bfloat16 h2 = __float2bfloat16(f.z), h3 = __float2bfloat16(f.w);
        __nv_bfloat162* hp = reinterpret_cast<__nv_bfloat162*>(g_ahi + 4 * (size_t)t);
        hp[0] = __nv_bfloat162(h0, h1);
        hp[1] = __nv_bfloat162(h2, h3);
        __nv_bfloat162* lp = reinterpret_cast<__nv_bfloat162*>(g_alo + 4 * (size_t)t);
        lp[0] = __nv_bfloat162(__float2bfloat16(f.x - __bfloat162float(h0)),
                               __float2bfloat16(f.y - __bfloat162float(h1)));
        lp[1] = __nv_bfloat162(__float2bfloat16(f.z - __bfloat162float(h2)),
                               __float2bfloat16(f.w - __bfloat162float(h3)));
    } else if (t < PREP_DEG) {
        g_deg[t - PREP_FEAT] = 0;
    } else if (t < PREP_ELZ) {
        int u = t - PREP_DEG;
        g_el[u] = 0.f;
        g_er[u] = 0.f;
    } else if (t < PREP_WLR) {
        int u = t - PREP_ELZ;
        int which = u >> 10;
        int hk = u & 1023;
        int h = hk >> 8, k = hk & 255;
        const float* a = (which == 0 ? al2 : ar2) + h * 256;
        const float* wrow = W2 + (size_t)k * 1024 + h * 256;
        float s = 0.f;
#pragma unroll 8
        for (int c = 0; c < 256; c++) s += wrow[c] * a[c];
        if (which == 0) g_wl2[hk] = s;
        else            g_wr2[hk] = s;
    } else if (t < PREP_B2) {
        int c = t - PREP_WLR;
        g_bias2[c] = 0.25f * (b2[c] + b2[256 + c] + b2[512 + c] + b2[768 + c]);
    } else if (t < PREP_W0) {
        int idx = t - PREP_B2;           // W0^T: [256,128]
        int n = idx >> 7, k = idx & 127;
        split1(W0[(size_t)k * 256 + n], g_b0hi, g_b0lo, idx);
    } else if (t < PREP_W1) {
        int idx = t - PREP_W0;           // W1^T: [256,256]
        int n = idx >> 8, k = idx & 255;
        split1(W1[(size_t)k * 256 + n], g_b1hi, g_b1lo, idx);
    } else if (t < PREP_TOT) {
        int idx = t - PREP_W1;           // W2 permuted: out[c][h*256+kk] = W2[kk*1024+h*256+c]
        int c = idx >> 10;
        int r = idx & 1023;
        int h = r >> 8, kk = r & 255;
        split1(W2[(size_t)kk * 1024 + h * 256 + c], g_b2hi, g_b2lo, idx);
    }
}

// zero el/er between layer-0 consumption and layer-1 GEMM score accumulation
__global__ void k_zeroel() {
    int t = blockIdx.x * blockDim.x + threadIdx.x;
    if (t < NN * NHEAD) {
        g_el[t] = 0.f;
        g_er[t] = 0.f;
    }
}

// ---------------- CSR build (by destination) ----------------
__global__ void k_count(const int* __restrict__ dst) {
    int i = blockIdx.x * blockDim.x + threadIdx.x;
    if (i < NE) atomicAdd(&g_deg[dst[i]], 1);
}

__global__ void k_scan1() {
    __shared__ int warpsum[32];
    int b = blockIdx.x, tid = threadIdx.x;
    int lane = tid & 31, wrp = tid >> 5;
    int i = b * 1024 + tid;
    int v = (i < NN) ? g_deg[i] : 0;
    int x = v;
#pragma unroll
    for (int o = 1; o < 32; o <<= 1) {
        int t = __shfl_up_sync(0xffffffffu, x, o);
        if (lane >= o) x += t;
    }
    if (lane == 31) warpsum[wrp] = x;
    __syncthreads();
    if (wrp == 0) {
        int w = warpsum[lane];
#pragma unroll
        for (int o = 1; o < 32; o <<= 1) {
            int t = __shfl_up_sync(0xffffffffu, w, o);
            if (lane >= o) w += t;
        }
        warpsum[lane] = w;
    }
    __syncthreads();
    int excl = (wrp ? warpsum[wrp - 1] : 0) + x - v;
    if (i < NN) g_off[i] = excl;
    if (tid == 0) g_bsum[b] = warpsum[31];
}

__global__ void k_scan2() {
    __shared__ int boff_s;
    int b = blockIdx.x, tid = threadIdx.x;
    if (tid == 0) boff_s = 0;
    __syncthreads();
    if (tid < b) atomicAdd(&boff_s, g_bsum[tid]);
    __syncthreads();
    int boff = boff_s;
    int i = b * 1024 + tid;
    if (i < NN) {
        int o = g_off[i] + boff;
        g_off[i] = o;
        g_cur[i] = o;
    }
    if (b == gridDim.x - 1 && tid == 0) g_off[NN] = boff + g_bsum[b];
}

__global__ void k_fill(const int* __restrict__ src, const int* __restrict__ dst) {
    int i = blockIdx.x * blockDim.x + threadIdx.x;
    if (i < NE) {
        int d = dst[i];
        int p = atomicAdd(&g_cur[d], 1);
        g_ss[p] = src[i];
    }
}

// ---------------- fused segment-softmax + aggregation ----------------
__device__ __forceinline__ float4 edge_score(const float* __restrict__ el, int s,
                                             const float4& er) {
    float4 l = *reinterpret_cast<const float4*>(&el[s * 4]);
    float4 v;
    float x;
    x = l.x + er.x; v.x = x > 0.f ? x : 0.2f * x;
    x = l.y + er.y; v.y = x > 0.f ? x : 0.2f * x;
    x = l.z + er.z; v.z = x > 0.f ? x : 0.2f * x;
    x = l.w + er.w; v.w = x > 0.f ? x : 0.2f * x;
    return v;
}

__device__ __forceinline__ void softmax_stats(const float* __restrict__ el, int j0, int j1,
                                              int lane, const float4& er, float* m, float* inv) {
    float s[NHEAD];
#pragma unroll
    for (int h = 0; h < NHEAD; h++) { m[h] = -FLT_MAX; s[h] = 0.f; }
    for (int j = j0 + lane; j < j1; j += 32) {
        float4 e4 = edge_score(el, g_ss[j], er);
        float ev[4] = {e4.x, e4.y, e4.z, e4.w};
#pragma unroll
        for (int h = 0; h < NHEAD; h++) {
            float nm = fmaxf(m[h], ev[h]);
            s[h] = s[h] * __expf(m[h] - nm) + __expf(ev[h] - nm);
            m[h] = nm;
        }
    }
#pragma unroll
    for (int h = 0; h < NHEAD; h++) {
#pragma unroll
        for (int o = 16; o > 0; o >>= 1) {
            float om = __shfl_xor_sync(0xffffffffu, m[h], o);
            float os = __shfl_xor_sync(0xffffffffu, s[h], o);
            float nm = fmaxf(m[h], om);
            s[h] = s[h] * __expf(m[h] - nm) + os * __expf(om - nm);
            m[h] = nm;
        }
    }
#pragma unroll
    for (int h = 0; h < NHEAD; h++) inv[h] = 1.f / fmaxf(s[h], 1e-9f);
}

__device__ __forceinline__ uint2 pack_hi4(const float* v) {
    __nv_bfloat162 p0(__float2bfloat16(v[0]), __float2bfloat16(v[1]));
    __nv_bfloat162 p1(__float2bfloat16(v[2]), __float2bfloat16(v[3]));
    uint2 r;
    r.x = *reinterpret_cast<uint32_t*>(&p0);
    r.y = *reinterpret_cast<uint32_t*>(&p1);
    return r;
}
__device__ __forceinline__ uint2 pack_lo4(const float* v) {
    float l0 = v[0] - __bfloat162float(__float2bfloat16(v[0]));
    float l1 = v[1] - __bfloat162float(__float2bfloat16(v[1]));
    float l2 = v[2] - __bfloat162float(__float2bfloat16(v[2]));
    float l3 = v[3] - __bfloat162float(__float2bfloat16(v[3]));
    __nv_bfloat162 p0(__float2bfloat16(l0), __float2bfloat16(l1));
    __nv_bfloat162 p1(__float2bfloat16(l2), __float2bfloat16(l3));
    uint2 r;
    r.x = *reinterpret_cast<uint32_t*>(&p0);
    r.y = *reinterpret_cast<uint32_t*>(&p1);
    return r;
}

// hidden layers; lane covers cols {c*128 + lane*4 .. +3}, c=0,1; head = c*2 + (lane>>4)
template <bool SC2>
__global__ void k_softagg_mid(const float* __restrict__ z, const float* __restrict__ bias,
                              float* __restrict__ hout) {
    int n = (blockIdx.x * blockDim.x + threadIdx.x) >> 5;
    int lane = threadIdx.x & 31;
    if (n >= NN) return;
    int j0 = g_off[n], j1 = g_off[n + 1];
    float4 er = *reinterpret_cast<const float4*>(&g_er[n * 4]);
    float m[NHEAD], inv[NHEAD];
    softmax_stats(g_el, j0, j1, lane, er, m, inv);

    int hA = lane >> 4;        // head for c=0
    int hB = 2 + (lane >> 4);  // head for c=1
    float acc0[4] = {0.f, 0.f, 0.f, 0.f};
    float acc1[4] = {0.f, 0.f, 0.f, 0.f};
#pragma unroll 2
    for (int j = j0; j < j1; j++) {
        int sidx = g_ss[j];
        float4 e4 = edge_score(g_el, sidx, er);
        float a[4];
        a[0] = __expf(e4.x - m[0]) * inv[0];
        a[1] = __expf(e4.y - m[1]) * inv[1];
        a[2] = __expf(e4.z - m[2]) * inv[2];
        a[3] = __expf(e4.w - m[3]) * inv[3];
        const float4* zr = reinterpret_cast<const float4*>(z + (size_t)sidx * 256);
        float4 f0 = zr[lane];
        float4 f1 = zr[32 + lane];
        float aA = a[hA], aB = a[hB];
        acc0[0] += aA * f0.x; acc0[1] += aA * f0.y; acc0[2] += aA * f0.z; acc0[3] += aA * f0.w;
        acc1[0] += aB * f1.x; acc1[1] += aB * f1.y; acc1[2] += aB * f1.z; acc1[3] += aB * f1.w;
    }

    float sl2[NHEAD], sr2[NHEAD];
    if (SC2) {
#pragma unroll
        for (int h = 0; h < NHEAD; h++) { sl2[h] = 0.f; sr2[h] = 0.f; }
    }
    const float4* b4 = reinterpret_cast<const float4*>(bias);
    size_t rowb = (size_t)n * 256;
#pragma unroll
    for (int c = 0; c < 2; c++) {
        float* acc = c ? acc1 : acc0;
        float4 bb = b4[c * 32 + lane];
        float v[4];
        v[0] = acc[0] + bb.x; v[1] = acc[1] + bb.y;
        v[2] = acc[2] + bb.z; v[3] = acc[3] + bb.w;
#pragma unroll
        for (int i = 0; i < 4; i++) v[i] = v[i] > 0.f ? v[i] : (__expf(v[i]) - 1.f);
        int col0 = c * 128 + lane * 4;
        *reinterpret_cast<float4*>(hout + rowb + col0) = make_float4(v[0], v[1], v[2], v[3]);
        *reinterpret_cast<uint2*>(g_ahi + rowb + col0) = pack_hi4(v);
        *reinterpret_cast<uint2*>(g_alo + rowb + col0) = pack_lo4(v);
        if (SC2) {
#pragma unroll
            for (int hh = 0; hh < NHEAD; hh++) {
                const float* wl = g_wl2 + hh * 256 + col0;
                const float* wr = g_wr2 + hh * 256 + col0;
#pragma unroll
                for (int i = 0; i < 4; i++) {
                    sl2[hh] += v[i] * wl[i];
                    sr2[hh] += v[i] * wr[i];
                }
            }
        }
    }
    if (SC2) {
#pragma unroll
        for (int hh = 0; hh < NHEAD; hh++) {
            float l = sl2[hh], r = sr2[hh];
#pragma unroll
            for (int o = 16; o > 0; o >>= 1) {
                l += __shfl_xor_sync(0xffffffffu, l, o);
                r += __shfl_xor_sync(0xffffffffu, r, o);
            }
            if (lane == 0) {
                g_el2[n * NHEAD + hh] = l;
                g_er2[n * NHEAD + hh] = r;
            }
        }
    }
}

// layer 2: softmax (el2/er2) + aggregate h1 into bf16 split A [N,1024]
__global__ void k_softagg2(const float* __restrict__ h1) {
    int n = (blockIdx.x * blockDim.x + threadIdx.x) >> 5;
    int lane = threadIdx.x & 31;
    if (n >= NN) return;
    int j0 = g_off[n], j1 = g_off[n + 1];
    float4 er = *reinterpret_cast<const float4*>(&g_er2[n * 4]);
    float m[NHEAD], inv[NHEAD];
    softmax_stats(g_el2, j0, j1, lane, er, m, inv);

    float acc[NHEAD][2][4];
#pragma unroll
    for (int h = 0; h < NHEAD; h++)
#pragma unroll
        for (int c = 0; c < 2; c++)
#pragma unroll
            for (int i = 0; i < 4; i++) acc[h][c][i] = 0.f;
#pragma unroll 2
    for (int j = j0; j < j1; j++) {
        int sidx = g_ss[j];
        float4 e4 = edge_score(g_el2, sidx, er);
        float a[4];
        a[0] = __expf(e4.x - m[0]) * inv[0];
        a[1] = __expf(e4.y - m[1]) * inv[1];
        a[2] = __expf(e4.z - m[2]) * inv[2];
        a[3] = __expf(e4.w - m[3]) * inv[3];
        const float4* hr = reinterpret_cast<const float4*>(h1 + (size_t)sidx * 256);
        float4 f0 = hr[lane];
        float4 f1 = hr[32 + lane];
#pragma unroll
        for (int h = 0; h < NHEAD; h++) {
            acc[h][0][0] += a[h] * f0.x; acc[h][0][1] += a[h] * f0.y;
            acc[h][0][2] += a[h] * f0.z; acc[h][0][3] += a[h] * f0.w;
            acc[h][1][0] += a[h] * f1.x; acc[h][1][1] += a[h] * f1.y;
            acc[h][1][2] += a[h] * f1.z; acc[h][1][3] += a[h] * f1.w;
        }
    }
    size_t base = (size_t)n * 1024;
#pragma unroll
    for (int h = 0; h < NHEAD; h++)
#pragma unroll
        for (int c = 0; c < 2; c++) {
            int col0 = h * 256 + c * 128 + lane * 4;
            *reinterpret_cast<uint2*>(g_ahi + base + col0) = pack_hi4(acc[h][c]);
            *reinterpret_cast<uint2*>(g_alo + base + col0) = pack_lo4(acc[h][c]);
        }
}

// ---------------- launch ----------------
extern "C" void kernel_launch(void* const* d_in, const int* in_sizes, int n_in,
                              void* d_out, int out_size) {
    const float* feat = (const float*)d_in[0];
    const float* W0 = (const float*)d_in[1];
    const float* al0 = (const float*)d_in[2];
    const float* ar0 = (const float*)d_in[3];
    const float* b0 = (const float*)d_in[4];
    const float* W1 = (const float*)d_in[5];
    const float* al1 = (const float*)d_in[6];
    const float* ar1 = (const float*)d_in[7];
    const float* b1 = (const float*)d_in[8];
    const float* W2 = (const float*)d_in[9];
    const float* al2 = (const float*)d_in[10];
    const float* ar2 = (const float*)d_in[11];
    const float* b2 = (const float*)d_in[12];
    const int* src = (const int*)d_in[13];
    const int* dst = (const int*)d_in[14];
    float* out = (float*)d_out;

    float *p_z, *p_h, *p_bias2;
    __nv_bfloat16 *p_ahi, *p_alo, *p_b0hi, *p_b0lo, *p_b1hi, *p_b1lo, *p_b2hi, *p_b2lo;
    cudaGetSymbolAddress((void**)&p_z, g_z);
    cudaGetSymbolAddress((void**)&p_h, g_h);
    cudaGetSymbolAddress((void**)&p_bias2, g_bias2);
    cudaGetSymbolAddress((void**)&p_ahi, g_ahi);
    cudaGetSymbolAddress((void**)&p_alo, g_alo);
    cudaGetSymbolAddress((void**)&p_b0hi, g_b0hi);
    cudaGetSymbolAddress((void**)&p_b0lo, g_b0lo);
    cudaGetSymbolAddress((void**)&p_b1hi, g_b1hi);
    cudaGetSymbolAddress((void**)&p_b1lo, g_b1lo);
    cudaGetSymbolAddress((void**)&p_b2hi, g_b2hi);
    cudaGetSymbolAddress((void**)&p_b2lo, g_b2lo);

    const int TB = 256;
    int eb = (NE + TB - 1) / TB;
    int nwb = (NN * 32 + TB - 1) / TB;   // one warp per node
    int scb = (NN + 1023) / 1024;
    dim3 ggrid(2, (NN + 127) / 128);

    // front: prep, then CSR chain with GEMM0 interleaved (4th launch for ncu visibility;
    // GEMM0 only depends on k_prep)
    k_prep<<<(PREP_TOT + TB - 1) / TB, TB>>>(feat, W0, W1, W2, al2, ar2, b2);
    k_count<<<eb, TB>>>(dst);
    k_scan1<<<scb, 1024>>>();
    k_gemm_mma<<<ggrid, 256>>>(p_ahi, p_alo, p_b0hi, p_b0lo, p_z, NN, 256, 128,
                               1.f, nullptr, al0, ar0);   // + fused el0/er0
    k_scan2<<<scb, 1024>>>();
    k_fill<<<eb, TB>>>(src, dst);

    // ---- layer 0: aggregate z0 -> h0 (ELU), split for GEMM1
    k_softagg_mid<false><<<nwb, TB>>>(p_z, b0, p_h);

    // ---- layer 1: zero scores, GEMM (+fused el1/er1), aggregate (+fused layer-2 scores)
    k_zeroel<<<(NN * NHEAD + TB - 1) / TB, TB>>>();
    k_gemm_mma<<<ggrid, 256>>>(p_ahi, p_alo, p_b1hi, p_b1lo, p_z, NN, 256, 256,
                               1.f, nullptr, al1, ar1);
    k_softagg_mid<true><<<nwb, TB>>>(p_z, b1, p_h);

    // ---- layer 2: softmax+aggregate h1, single GEMM K=1024
    k_softagg2<<<nwb, TB>>>(p_h);
    k_gemm_mma<<<ggrid, 256>>>(p_ahi, p_alo, p_b2hi, p_b2lo, out, NN, 256, 1024,
                               0.25f, p_bias2, nullptr, nullptr);
}